// round 10
// baseline (speedup 1.0000x reference)
#include <cuda_runtime.h>
#include <math.h>

#define BB   4
#define HWSZ 16384        // 128*128
#define NEGINF (-1000000000.0f)

// ---------------- scratch (device globals: no allocation allowed) ----------------
__device__ float g_value[ 8388608];  // (4,128,128,128)
__device__ float g_pv   [ 8388608];
__device__ float g_tmp  [ 8388608];
__device__ float g_pq   [ 1048576];  // (4,16,128,128)
__device__ float g_pk   [ 1048576];
__device__ float g_att  [16777216];  // (4,128,128,256)
__device__ float g_pqs  [  262144];  // (4,16,64,64)
__device__ float g_vs   [ 2097152];  // (4,128,64,64)
__device__ float g_fbs  [ 4194304];  // (4,256,64,64)  Wb_hi@high, low-res
__device__ float g_weff [    8192];  // Wq@Wc1 (16,512)
__device__ float g_beff [      16];

// ---------------- tf32 helpers ----------------
__device__ __forceinline__ unsigned f2tf(float f) {
    unsigned r;
    asm("cvt.rna.tf32.f32 %0, %1;" : "=r"(r) : "f"(f));
    return r;
}

__device__ __forceinline__ void mma8(float* d, const unsigned* a, const unsigned* b) {
    asm("mma.sync.aligned.m16n8k8.row.col.f32.tf32.tf32.f32 "
        "{%0,%1,%2,%3},{%4,%5,%6,%7},{%8,%9},{%0,%1,%2,%3};"
        : "+f"(d[0]), "+f"(d[1]), "+f"(d[2]), "+f"(d[3])
        : "r"(a[0]), "r"(a[1]), "r"(a[2]), "r"(a[3]), "r"(b[0]), "r"(b[1]));
}

__device__ __forceinline__ void tile_mma(const unsigned (*As)[136],
                                         const unsigned (*Bs)[136],
                                         float acc[4][4][4],
                                         int lane, int mbase, int nbase)
{
#pragma unroll
    for (int kt = 0; kt < 2; kt++) {
        unsigned a[4][4], b[4][2];
        const int kb = kt * 8 + (lane & 3);
        const int rq = lane >> 2;
#pragma unroll
        for (int mt = 0; mt < 4; mt++) {
            int m = mbase + mt * 16 + rq;
            a[mt][0] = As[kb][m];
            a[mt][1] = As[kb][m + 8];
            a[mt][2] = As[kb + 4][m];
            a[mt][3] = As[kb + 4][m + 8];
        }
#pragma unroll
        for (int nt = 0; nt < 4; nt++) {
            int n = nbase + nt * 8 + rq;
            b[nt][0] = Bs[kb][n];
            b[nt][1] = Bs[kb + 4][n];
        }
#pragma unroll
        for (int mt = 0; mt < 4; mt++)
#pragma unroll
            for (int nt = 0; nt < 4; nt++)
                mma8(acc[mt][nt], a[mt], b[nt]);
    }
}

// ---------------- Wq_eff = Wq @ Wc1 ; b_eff = bq + Wq @ bc1 ----------------
__global__ __launch_bounds__(256) void prep_weff(
    const float* __restrict__ Wq, const float* __restrict__ Wc1,
    const float* __restrict__ bq, const float* __restrict__ bc1,
    float* __restrict__ weff, float* __restrict__ beff)
{
    int t = blockIdx.x * 256 + threadIdx.x;
    if (blockIdx.x < 32) {
        int o = t >> 9, j = t & 511;
        float s = 0.0f;
#pragma unroll 4
        for (int i = 0; i < 128; i++) s += Wq[o * 128 + i] * Wc1[i * 512 + j];
        weff[o * 512 + j] = s;
    } else if (threadIdx.x < 16) {
        int o = threadIdx.x;
        float s = bq[o];
        for (int i = 0; i < 128; i++) s += Wq[o * 128 + i] * bc1[i];
        beff[o] = s;
    }
}

// ---------------- bilinear 2x upsample ----------------
__global__ __launch_bounds__(256) void upsample_kernel(const float* __restrict__ in,
                                                       float* __restrict__ out) {
    int idx = blockIdx.x * 256 + threadIdx.x;
    int ox = idx & 127;
    int oy = (idx >> 7) & 127;
    int bc = idx >> 14;
    float fy = 0.5f * oy - 0.25f;
    float fx = 0.5f * ox - 0.25f;
    int y0 = (int)floorf(fy); float wy = fy - (float)y0;
    int x0 = (int)floorf(fx); float wx = fx - (float)x0;
    int y1 = min(y0 + 1, 63); y0 = max(y0, 0);
    int x1 = min(x0 + 1, 63); x0 = max(x0, 0);
    const float* p = in + (size_t)bc * 4096;
    float v00 = p[y0 * 64 + x0], v01 = p[y0 * 64 + x1];
    float v10 = p[y1 * 64 + x0], v11 = p[y1 * 64 + x1];
    float top = v00 + wx * (v01 - v00);
    float bot = v10 + wx * (v11 - v10);
    out[idx] = top + wy * (bot - top);
}

// ---------------- tf32 GEMM: Y[b,o,p] = W@X (+inline-upsampled fbs) (+BN/ReLU) -------
// If fbsp != nullptr: hw must be HWSZ; adds bilinear-upsampled fbs[b,o] before BN.
__global__ __launch_bounds__(256) void gemm_dual(
    const float* __restrict__ Wm, int ldw,
    const float* __restrict__ bias,
    const float* __restrict__ X, int I,
    float* __restrict__ Y, int O, int hw,
    const float* __restrict__ fbsp,
    const float* __restrict__ bng, const float* __restrict__ bnb,
    const float* __restrict__ bnm, const float* __restrict__ bnv)
{
    __shared__ unsigned As[16][136];
    __shared__ unsigned Bs[16][136];
    const int b  = blockIdx.z;
    const int to = blockIdx.y * 128;
    const int tp = blockIdx.x * 128;
    const int tid  = threadIdx.x;
    const int warp = tid >> 5;
    const int lane = tid & 31;
    const int mbase = (warp >> 2) * 64;
    const int nbase = (warp & 3) * 32;

    const int am  = tid >> 1;
    const int akq = (tid & 1) * 8;
    const int bk  = tid >> 4;
    const int bn  = (tid & 15) * 8;

    const float* Xp0 = X + (size_t)b * I * hw + tp + bn;

    float acc[4][4][4] = {};

    for (int k0 = 0; k0 < I; k0 += 16) {
        const float* Wp = Wm + (size_t)(to + am) * ldw + k0 + akq;
        float4 w0 = *(const float4*)Wp;
        float4 w1 = *(const float4*)(Wp + 4);
        const float* Xp = Xp0 + (size_t)(k0 + bk) * hw;
        float4 x0 = *(const float4*)Xp;
        float4 x1 = *(const float4*)(Xp + 4);

        __syncthreads();
        As[akq + 0][am] = f2tf(w0.x);
        As[akq + 1][am] = f2tf(w0.y);
        As[akq + 2][am] = f2tf(w0.z);
        As[akq + 3][am] = f2tf(w0.w);
        As[akq + 4][am] = f2tf(w1.x);
        As[akq + 5][am] = f2tf(w1.y);
        As[akq + 6][am] = f2tf(w1.z);
        As[akq + 7][am] = f2tf(w1.w);
        *(uint4*)&Bs[bk][bn]     = make_uint4(f2tf(x0.x), f2tf(x0.y), f2tf(x0.z), f2tf(x0.w));
        *(uint4*)&Bs[bk][bn + 4] = make_uint4(f2tf(x1.x), f2tf(x1.y), f2tf(x1.z), f2tf(x1.w));
        __syncthreads();

        tile_mma(As, Bs, acc, lane, mbase, nbase);
    }

    // inline upsample y-coords (h constant per block when fbsp used, hw==HWSZ)
    int y0i = 0, y1i = 0; float wy = 0.0f;
    if (fbsp) {
        int h = tp >> 7;
        float fy = 0.5f * h - 0.25f;
        y0i = (int)floorf(fy); wy = fy - (float)y0i;
        y1i = min(y0i + 1, 63); y0i = max(y0i, 0);
    }

    const bool dobn = (bng != nullptr);
#pragma unroll
    for (int mt = 0; mt < 4; mt++) {
#pragma unroll
        for (int half = 0; half < 2; half++) {
            int o = to + mbase + mt * 16 + (lane >> 2) + half * 8;
            float bia = bias ? bias[o] : 0.0f;
            float sc = 1.0f, mn = 0.0f, bt = 0.0f;
            if (dobn) {
                sc = bng[o] * rsqrtf(bnv[o] + 1e-5f);
                mn = bnm[o];
                bt = bnb[o];
            }
            const float* fb0 = nullptr; const float* fb1 = nullptr;
            if (fbsp) {
                const float* fb = fbsp + ((size_t)b * 256 + o) * 4096;
                fb0 = fb + y0i * 64;
                fb1 = fb + y1i * 64;
            }
            size_t rowb = ((size_t)b * O + o) * hw + tp;
#pragma unroll
            for (int nt = 0; nt < 4; nt++) {
                int n = nbase + nt * 8 + 2 * (lane & 3);
                float v0 = acc[mt][nt][half * 2 + 0] + bia;
                float v1 = acc[mt][nt][half * 2 + 1] + bia;
                if (fbsp) {
#pragma unroll
                    for (int q = 0; q < 2; q++) {
                        int w = n + q;
                        float fx = 0.5f * w - 0.25f;
                        int x0 = (int)floorf(fx); float wx = fx - (float)x0;
                        int x1 = min(x0 + 1, 63); x0 = max(x0, 0);
                        float top = fb0[x0] + wx * (fb0[x1] - fb0[x0]);
                        float bot = fb1[x0] + wx * (fb1[x1] - fb1[x0]);
                        float u = top + wy * (bot - top);
                        if (q == 0) v0 += u; else v1 += u;
                    }
                }
                if (dobn) {
                    v0 = fmaxf((v0 - mn) * sc + bt, 0.0f);
                    v1 = fmaxf((v1 - mn) * sc + bt, 0.0f);
                }
                *(float2*)(Y + rowb + n) = make_float2(v0, v1);
            }
        }
    }
}

// ---------------- generic 16-output projection ----------------
__global__ __launch_bounds__(256) void proj16g(
    const float* __restrict__ Wm, int ldw,
    const float* __restrict__ bias,
    const float* __restrict__ X, int K, int hw,
    float* __restrict__ Y, int accum)
{
    __shared__ float Ws[16 * 256];
    const int b = blockIdx.y;
    const int p = blockIdx.x * 256 + threadIdx.x;
    for (int i = threadIdx.x; i < 16 * K; i += 256)
        Ws[i] = Wm[(i / K) * ldw + (i % K)];
    __syncthreads();
    float* Yp = Y + (size_t)b * 16 * hw + p;
    float acc[16];
#pragma unroll
    for (int o = 0; o < 16; o++)
        acc[o] = accum ? Yp[(size_t)o * hw] : (bias ? bias[o] : 0.0f);
    const float* Xp = X + (size_t)b * K * hw + p;
#pragma unroll 4
    for (int i = 0; i < K; i++) {
        float xv = Xp[(size_t)i * hw];
#pragma unroll
        for (int o = 0; o < 16; o++) acc[o] += Ws[o * K + i] * xv;
    }
#pragma unroll
    for (int o = 0; o < 16; o++) Yp[(size_t)o * hw] = acc[o];
}

// ---------------- split-K 16-output projection for K=256 @ HWSZ (accumulates into Y) ----
// 2 threads per pixel; each covers 128 K-channels; combine through padded smem.
__global__ __launch_bounds__(256) void proj16_splitk(
    const float* __restrict__ Wm, int ldw,          // Wm[o*ldw + k], k in [0,256)
    const float* __restrict__ X,                    // (b,256,HWSZ)
    float* __restrict__ Y)                          // (b,16,HWSZ), accumulated
{
    __shared__ float Wsh[2][16 * 128];
    __shared__ float part[128][17];
    const int b  = blockIdx.y;
    const int px0 = blockIdx.x * 128;
    const int tid = threadIdx.x;
    const int pi = tid & 127;
    const int kh = tid >> 7;

    for (int i = tid; i < 4096; i += 256) {
        int o = i >> 8, k = i & 255;
        Wsh[k >> 7][o * 128 + (k & 127)] = Wm[o * ldw + k];
    }
    __syncthreads();

    float acc[16] = {};
    const float* Xp = X + ((size_t)b * 256 + kh * 128) * HWSZ + px0 + pi;
    const float* Wk = Wsh[kh];
#pragma unroll 4
    for (int i = 0; i < 128; i++) {
        float xv = Xp[(size_t)i * HWSZ];
#pragma unroll
        for (int o = 0; o < 16; o++) acc[o] += Wk[o * 128 + i] * xv;
    }

    if (kh == 1) {
#pragma unroll
        for (int o = 0; o < 16; o++) part[pi][o] = acc[o];
    }
    __syncthreads();
    if (kh == 0) {
        float* Yp = Y + (size_t)b * 16 * HWSZ + px0 + pi;
#pragma unroll
        for (int o = 0; o < 16; o++)
            Yp[(size_t)o * HWSZ] += acc[o] + part[pi][o];
    }
}

// ---------------- merged criss-cross logits (mode 0 = eH, 1 = eW) ----------------
__global__ __launch_bounds__(256) void e_both_kernel(const float* __restrict__ pq,
                                                     const float* __restrict__ pk,
                                                     float* __restrict__ att)
{
    __shared__ float PQ[16][128];
    __shared__ float PK[16][128];
    const int fix = blockIdx.x, b = blockIdx.y, mode = blockIdx.z;
    for (int i = threadIdx.x; i < 2048; i += 256) {
        int c = i >> 7, r = i & 127;
        // mode 0: fixed w=fix, varying h=r.  mode 1: fixed h=fix, varying w=r.
        size_t idx = (mode == 0)
            ? (((size_t)b * 16 + c) * 128 + r) * 128 + fix
            : (((size_t)b * 16 + c) * 128 + fix) * 128 + r;
        PQ[c][r] = pq[idx];
        PK[c][r] = pk[idx];
    }
    __syncthreads();
    const int x  = threadIdx.x & 127;
    const int r0 = threadIdx.x >> 7;
    for (int r = r0; r < 128; r += 2) {
        float s = 0.0f;
#pragma unroll
        for (int c = 0; c < 16; c++) s += PQ[c][r] * PK[c][x];
        if (mode == 0) {
            if (r == x) s += NEGINF;
            att[(((size_t)b * 128 + r) * 128 + fix) * 256 + x] = s;
        } else {
            att[(((size_t)b * 128 + fix) * 128 + r) * 256 + 128 + x] = s;
        }
    }
}

__global__ __launch_bounds__(256) void softmax_kernel(float* __restrict__ att)
{
    const int warp = threadIdx.x >> 5;
    const int lane = threadIdx.x & 31;
    const size_t row = (size_t)blockIdx.x * 8 + warp;
    float* r = att + row * 256;
    float v[8];
    float mx = -INFINITY;
#pragma unroll
    for (int j = 0; j < 8; j++) { v[j] = r[lane + 32 * j]; mx = fmaxf(mx, v[j]); }
#pragma unroll
    for (int o = 16; o; o >>= 1) mx = fmaxf(mx, __shfl_xor_sync(0xffffffffu, mx, o));
    float s = 0.0f;
#pragma unroll
    for (int j = 0; j < 8; j++) { v[j] = __expf(v[j] - mx); s += v[j]; }
#pragma unroll
    for (int o = 16; o; o >>= 1) s += __shfl_xor_sync(0xffffffffu, s, o);
    float inv = 1.0f / s;
#pragma unroll
    for (int j = 0; j < 8; j++) r[lane + 32 * j] = v[j] * inv;
}

// ---------------- aggH: tmp[b,c,h,w] = sum_x pv[b,c,x,w]*attH[b,h,w,x] ----------------
__global__ __launch_bounds__(256) void aggH_mma(const float* __restrict__ pv,
                                                const float* __restrict__ att,
                                                float* __restrict__ tmp)
{
    __shared__ unsigned As[16][136];
    __shared__ unsigned Bs[16][136];
    const int w = blockIdx.x, b = blockIdx.y;
    const int tid  = threadIdx.x;
    const int warp = tid >> 5;
    const int lane = tid & 31;
    const int mbase = (warp >> 2) * 64;
    const int nbase = (warp & 3) * 32;

    const int cm = tid >> 1;
    const int xq = (tid & 1) * 8;

    float acc[4][4][4] = {};
    const float* pvp = pv + ((size_t)b * 128 + cm) * HWSZ + w;
    const float* atp = att + (((size_t)b * 128 + cm) * 128 + w) * 256;

    for (int k0 = 0; k0 < 128; k0 += 16) {
        float av[8];
#pragma unroll
        for (int j = 0; j < 8; j++) av[j] = pvp[(size_t)(k0 + xq + j) * 128];
        float4 b0 = *(const float4*)(atp + k0 + xq);
        float4 b1 = *(const float4*)(atp + k0 + xq + 4);

        __syncthreads();
#pragma unroll
        for (int j = 0; j < 8; j++) As[xq + j][cm] = f2tf(av[j]);
        Bs[xq + 0][cm] = f2tf(b0.x);
        Bs[xq + 1][cm] = f2tf(b0.y);
        Bs[xq + 2][cm] = f2tf(b0.z);
        Bs[xq + 3][cm] = f2tf(b0.w);
        Bs[xq + 4][cm] = f2tf(b1.x);
        Bs[xq + 5][cm] = f2tf(b1.y);
        Bs[xq + 6][cm] = f2tf(b1.z);
        Bs[xq + 7][cm] = f2tf(b1.w);
        __syncthreads();

        tile_mma(As, Bs, acc, lane, mbase, nbase);
    }

#pragma unroll
    for (int mt = 0; mt < 4; mt++)
#pragma unroll
        for (int half = 0; half < 2; half++) {
            int c = mbase + mt * 16 + (lane >> 2) + half * 8;
            size_t cb = ((size_t)b * 128 + c) * HWSZ + w;
#pragma unroll
            for (int nt = 0; nt < 4; nt++) {
                int h = nbase + nt * 8 + 2 * (lane & 3);
                tmp[cb + (size_t)h * 128]       = acc[mt][nt][half * 2 + 0];
                tmp[cb + (size_t)(h + 1) * 128] = acc[mt][nt][half * 2 + 1];
            }
        }
}

// ---------------- aggW + update: value += gamma*(tmp + sum_x pv*attW) ----------------
__global__ __launch_bounds__(256) void aggW_mma(const float* __restrict__ pv,
                                                const float* __restrict__ att,
                                                const float* __restrict__ tmp,
                                                float* __restrict__ value,
                                                const float* __restrict__ gamma_p)
{
    __shared__ unsigned As[16][136];
    __shared__ unsigned Bs[16][136];
    const int h = blockIdx.x, b = blockIdx.y;
    const int tid  = threadIdx.x;
    const int warp = tid >> 5;
    const int lane = tid & 31;
    const int mbase = (warp >> 2) * 64;
    const int nbase = (warp & 3) * 32;

    const int cm = tid >> 1;
    const int xq = (tid & 1) * 8;

    float acc[4][4][4] = {};
    const float* pvp = pv + (((size_t)b * 128 + cm) * 128 + h) * 128;
    const float* atp = att + (((size_t)b * 128 + h) * 128 + cm) * 256 + 128;

    for (int k0 = 0; k0 < 128; k0 += 16) {
        float4 a0 = *(const float4*)(pvp + k0 + xq);
        float4 a1 = *(const float4*)(pvp + k0 + xq + 4);
        float4 b0 = *(const float4*)(atp + k0 + xq);
        float4 b1 = *(const float4*)(atp + k0 + xq + 4);

        __syncthreads();
        As[xq + 0][cm] = f2tf(a0.x);
        As[xq + 1][cm] = f2tf(a0.y);
        As[xq + 2][cm] = f2tf(a0.z);
        As[xq + 3][cm] = f2tf(a0.w);
        As[xq + 4][cm] = f2tf(a1.x);
        As[xq + 5][cm] = f2tf(a1.y);
        As[xq + 6][cm] = f2tf(a1.z);
        As[xq + 7][cm] = f2tf(a1.w);
        Bs[xq + 0][cm] = f2tf(b0.x);
        Bs[xq + 1][cm] = f2tf(b0.y);
        Bs[xq + 2][cm] = f2tf(b0.z);
        Bs[xq + 3][cm] = f2tf(b0.w);
        Bs[xq + 4][cm] = f2tf(b1.x);
        Bs[xq + 5][cm] = f2tf(b1.y);
        Bs[xq + 6][cm] = f2tf(b1.z);
        Bs[xq + 7][cm] = f2tf(b1.w);
        __syncthreads();

        tile_mma(As, Bs, acc, lane, mbase, nbase);
    }

    const float g = *gamma_p;
#pragma unroll
    for (int mt = 0; mt < 4; mt++)
#pragma unroll
        for (int half = 0; half < 2; half++) {
            int c = mbase + mt * 16 + (lane >> 2) + half * 8;
            size_t rowb = (((size_t)b * 128 + c) * 128 + h) * 128;
#pragma unroll
            for (int nt = 0; nt < 4; nt++) {
                int n = nbase + nt * 8 + 2 * (lane & 3);
                float2 t = *(const float2*)(tmp + rowb + n);
                float2 v = *(const float2*)(value + rowb + n);
                v.x += g * (t.x + acc[mt][nt][half * 2 + 0]);
                v.y += g * (t.y + acc[mt][nt][half * 2 + 1]);
                *(float2*)(value + rowb + n) = v;
            }
        }
}

// ---------------- launch ----------------
extern "C" void kernel_launch(void* const* d_in, const int* in_sizes, int n_in,
                              void* d_out, int out_size)
{
    const float* low   = (const float*)d_in[0];
    const float* high  = (const float*)d_in[1];
    const float* Wc1   = (const float*)d_in[2];
    const float* bc1   = (const float*)d_in[3];
    const float* Wc2   = (const float*)d_in[4];
    const float* bc2   = (const float*)d_in[5];
    const float* Wq    = (const float*)d_in[6];
    const float* bq    = (const float*)d_in[7];
    const float* Wk    = (const float*)d_in[8];
    const float* bk    = (const float*)d_in[9];
    const float* Wv    = (const float*)d_in[10];
    const float* bv    = (const float*)d_in[11];
    const float* gamma = (const float*)d_in[12];
    const float* Wb    = (const float*)d_in[13];
    const float* bng   = (const float*)d_in[14];
    const float* bnb   = (const float*)d_in[15];
    const float* bnm   = (const float*)d_in[16];
    const float* bnv   = (const float*)d_in[17];
    float* out = (float*)d_out;

    float *value, *pv, *tmp, *pq, *pk, *att, *pqs, *vs, *fbs, *weff, *beff;
    cudaGetSymbolAddress((void**)&value, g_value);
    cudaGetSymbolAddress((void**)&pv,    g_pv);
    cudaGetSymbolAddress((void**)&tmp,   g_tmp);
    cudaGetSymbolAddress((void**)&pq,    g_pq);
    cudaGetSymbolAddress((void**)&pk,    g_pk);
    cudaGetSymbolAddress((void**)&att,   g_att);
    cudaGetSymbolAddress((void**)&pqs,   g_pqs);
    cudaGetSymbolAddress((void**)&vs,    g_vs);
    cudaGetSymbolAddress((void**)&fbs,   g_fbs);
    cudaGetSymbolAddress((void**)&weff,  g_weff);
    cudaGetSymbolAddress((void**)&beff,  g_beff);

    // 0. fold Wq through Wc1 (query tensor never materialized)
    prep_weff<<<33, 256>>>(Wq, Wc1, bq, bc1, weff, beff);

    // 1. pq = upsample(Wq_eff_hi @ high) + Wq_eff_lo @ low  (split-K for the low half)
    proj16g<<<dim3(16, BB), 256>>>(weff, 512, beff, high, 256, 4096, pqs, 0);
    upsample_kernel<<<4096, 256>>>(pqs, pq);
    proj16_splitk<<<dim3(128, BB), 256>>>(weff + 256, 512, low, pq);

    // 2. value = upsample(Wc2 @ high + bc2)
    gemm_dual<<<dim3(32, 1, BB), 256>>>(Wc2, 256, bc2, high, 256, vs, 128, 4096,
                                        nullptr, nullptr, nullptr, nullptr, nullptr);
    upsample_kernel<<<32768, 256>>>(vs, value);

    // 3. fbs = Wb[:,128:] @ high  (low-res; upsample folded into final epilogue)
    gemm_dual<<<dim3(32, 2, BB), 256>>>(Wb + 128, 384, nullptr, high, 256, fbs, 256, 4096,
                                        nullptr, nullptr, nullptr, nullptr, nullptr);

    // 4. two criss-cross attention iterations
    for (int it = 0; it < 2; it++) {
        proj16g<<<dim3(64, BB), 256>>>(Wk, 128, bk, value, 128, HWSZ, pk, 0);
        gemm_dual<<<dim3(128, 1, BB), 256>>>(Wv, 128, bv, value, 128, pv, 128, HWSZ,
                                             nullptr, nullptr, nullptr, nullptr, nullptr);
        e_both_kernel<<<dim3(128, BB, 2), 256>>>(pq, pk, att);
        softmax_kernel<<<8192, 256>>>(att);
        aggH_mma<<<dim3(128, BB), 256>>>(pv, att, tmp);
        aggW_mma<<<dim3(128, BB), 256>>>(pv, att, tmp, value, gamma);
    }

    // 5. out = ReLU(BN(Wb[:,:128] @ value + upsample(fbs)))  (upsample inline)
    gemm_dual<<<dim3(128, 2, BB), 256>>>(Wb, 384, nullptr, value, 128, out, 256, HWSZ,
                                         fbs, bng, bnb, bnm, bnv);
}

// round 11
// speedup vs baseline: 1.0674x; 1.0674x over previous
#include <cuda_runtime.h>
#include <math.h>

#define BB   4
#define HWSZ 16384        // 128*128
#define NEGINF (-1000000000.0f)

// ---------------- scratch (device globals: no allocation allowed) ----------------
__device__ float g_fbu  [16777216];  // upsampled Wb_hi@high (4,256,128,128)
__device__ float g_value[ 8388608];  // (4,128,128,128)
__device__ float g_pv   [ 8388608];
__device__ float g_tmp  [ 8388608];
__device__ float g_pq   [ 1048576];  // (4,16,128,128)
__device__ float g_pk   [ 1048576];
__device__ float g_att  [16777216];  // (4,128,128,256) raw logits
__device__ float g_pqs  [  262144];  // (4,16,64,64)
__device__ float g_vs   [ 2097152];  // (4,128,64,64)
__device__ float g_fbs  [ 4194304];  // (4,256,64,64)
__device__ float g_weff [    8192];  // Wq@Wc1 (16,512)
__device__ float g_beff [      16];
__device__ float g_mrow [   65536];  // per-row max
__device__ float g_irow [   65536];  // per-row 1/sum

// ---------------- tf32 helpers ----------------
__device__ __forceinline__ unsigned f2tf(float f) {
    unsigned r;
    asm("cvt.rna.tf32.f32 %0, %1;" : "=r"(r) : "f"(f));
    return r;
}

__device__ __forceinline__ void mma8(float* d, const unsigned* a, const unsigned* b) {
    asm("mma.sync.aligned.m16n8k8.row.col.f32.tf32.tf32.f32 "
        "{%0,%1,%2,%3},{%4,%5,%6,%7},{%8,%9},{%0,%1,%2,%3};"
        : "+f"(d[0]), "+f"(d[1]), "+f"(d[2]), "+f"(d[3])
        : "r"(a[0]), "r"(a[1]), "r"(a[2]), "r"(a[3]), "r"(b[0]), "r"(b[1]));
}

__device__ __forceinline__ void tile_mma(const unsigned (*As)[136],
                                         const unsigned (*Bs)[136],
                                         float acc[4][4][4],
                                         int lane, int mbase, int nbase)
{
#pragma unroll
    for (int kt = 0; kt < 2; kt++) {
        unsigned a[4][4], b[4][2];
        const int kb = kt * 8 + (lane & 3);
        const int rq = lane >> 2;
#pragma unroll
        for (int mt = 0; mt < 4; mt++) {
            int m = mbase + mt * 16 + rq;
            a[mt][0] = As[kb][m];
            a[mt][1] = As[kb][m + 8];
            a[mt][2] = As[kb + 4][m];
            a[mt][3] = As[kb + 4][m + 8];
        }
#pragma unroll
        for (int nt = 0; nt < 4; nt++) {
            int n = nbase + nt * 8 + rq;
            b[nt][0] = Bs[kb][n];
            b[nt][1] = Bs[kb + 4][n];
        }
#pragma unroll
        for (int mt = 0; mt < 4; mt++)
#pragma unroll
            for (int nt = 0; nt < 4; nt++)
                mma8(acc[mt][nt], a[mt], b[nt]);
    }
}

// ---------------- Wq_eff = Wq @ Wc1 ; b_eff = bq + Wq @ bc1 ----------------
__global__ __launch_bounds__(256) void prep_weff(
    const float* __restrict__ Wq, const float* __restrict__ Wc1,
    const float* __restrict__ bq, const float* __restrict__ bc1,
    float* __restrict__ weff, float* __restrict__ beff)
{
    int t = blockIdx.x * 256 + threadIdx.x;
    if (blockIdx.x < 32) {
        int o = t >> 9, j = t & 511;
        float s = 0.0f;
#pragma unroll 4
        for (int i = 0; i < 128; i++) s += Wq[o * 128 + i] * Wc1[i * 512 + j];
        weff[o * 512 + j] = s;
    } else if (threadIdx.x < 16) {
        int o = threadIdx.x;
        float s = bq[o];
        for (int i = 0; i < 128; i++) s += Wq[o * 128 + i] * bc1[i];
        beff[o] = s;
    }
}

// ---------------- bilinear 2x upsample ----------------
__global__ __launch_bounds__(256) void upsample_kernel(const float* __restrict__ in,
                                                       float* __restrict__ out) {
    int idx = blockIdx.x * 256 + threadIdx.x;
    int ox = idx & 127;
    int oy = (idx >> 7) & 127;
    int bc = idx >> 14;
    float fy = 0.5f * oy - 0.25f;
    float fx = 0.5f * ox - 0.25f;
    int y0 = (int)floorf(fy); float wy = fy - (float)y0;
    int x0 = (int)floorf(fx); float wx = fx - (float)x0;
    int y1 = min(y0 + 1, 63); y0 = max(y0, 0);
    int x1 = min(x0 + 1, 63); x0 = max(x0, 0);
    const float* p = in + (size_t)bc * 4096;
    float v00 = p[y0 * 64 + x0], v01 = p[y0 * 64 + x1];
    float v10 = p[y1 * 64 + x0], v11 = p[y1 * 64 + x1];
    float top = v00 + wx * (v01 - v00);
    float bot = v10 + wx * (v11 - v10);
    out[idx] = top + wy * (bot - top);
}

// ---------------- tf32 GEMM: Y[b,o,p] = W@X (+addin) (+BN/ReLU) ----------------
__global__ __launch_bounds__(256) void gemm_dual(
    const float* __restrict__ Wm, int ldw,
    const float* __restrict__ bias,
    const float* __restrict__ X, int I,
    float* __restrict__ Y, int O, int hw,
    const float* __restrict__ addin,
    const float* __restrict__ bng, const float* __restrict__ bnb,
    const float* __restrict__ bnm, const float* __restrict__ bnv)
{
    __shared__ unsigned As[16][136];
    __shared__ unsigned Bs[16][136];
    const int b  = blockIdx.z;
    const int to = blockIdx.y * 128;
    const int tp = blockIdx.x * 128;
    const int tid  = threadIdx.x;
    const int warp = tid >> 5;
    const int lane = tid & 31;
    const int mbase = (warp >> 2) * 64;
    const int nbase = (warp & 3) * 32;

    const int am  = tid >> 1;
    const int akq = (tid & 1) * 8;
    const int bk  = tid >> 4;
    const int bn  = (tid & 15) * 8;

    const float* Xp0 = X + (size_t)b * I * hw + tp + bn;

    float acc[4][4][4] = {};

    for (int k0 = 0; k0 < I; k0 += 16) {
        const float* Wp = Wm + (size_t)(to + am) * ldw + k0 + akq;
        float4 w0 = *(const float4*)Wp;
        float4 w1 = *(const float4*)(Wp + 4);
        const float* Xp = Xp0 + (size_t)(k0 + bk) * hw;
        float4 x0 = *(const float4*)Xp;
        float4 x1 = *(const float4*)(Xp + 4);

        __syncthreads();
        As[akq + 0][am] = f2tf(w0.x);
        As[akq + 1][am] = f2tf(w0.y);
        As[akq + 2][am] = f2tf(w0.z);
        As[akq + 3][am] = f2tf(w0.w);
        As[akq + 4][am] = f2tf(w1.x);
        As[akq + 5][am] = f2tf(w1.y);
        As[akq + 6][am] = f2tf(w1.z);
        As[akq + 7][am] = f2tf(w1.w);
        *(uint4*)&Bs[bk][bn]     = make_uint4(f2tf(x0.x), f2tf(x0.y), f2tf(x0.z), f2tf(x0.w));
        *(uint4*)&Bs[bk][bn + 4] = make_uint4(f2tf(x1.x), f2tf(x1.y), f2tf(x1.z), f2tf(x1.w));
        __syncthreads();

        tile_mma(As, Bs, acc, lane, mbase, nbase);
    }

    const bool dobn = (bng != nullptr);
#pragma unroll
    for (int mt = 0; mt < 4; mt++) {
#pragma unroll
        for (int half = 0; half < 2; half++) {
            int o = to + mbase + mt * 16 + (lane >> 2) + half * 8;
            float bia = bias ? bias[o] : 0.0f;
            float sc = 1.0f, mn = 0.0f, bt = 0.0f;
            if (dobn) {
                sc = bng[o] * rsqrtf(bnv[o] + 1e-5f);
                mn = bnm[o];
                bt = bnb[o];
            }
            size_t rowb = ((size_t)b * O + o) * hw + tp;
#pragma unroll
            for (int nt = 0; nt < 4; nt++) {
                int n = nbase + nt * 8 + 2 * (lane & 3);
                float v0 = acc[mt][nt][half * 2 + 0] + bia;
                float v1 = acc[mt][nt][half * 2 + 1] + bia;
                if (addin) {
                    float2 ad = *(const float2*)(addin + rowb + n);
                    v0 += ad.x; v1 += ad.y;
                }
                if (dobn) {
                    v0 = fmaxf((v0 - mn) * sc + bt, 0.0f);
                    v1 = fmaxf((v1 - mn) * sc + bt, 0.0f);
                }
                *(float2*)(Y + rowb + n) = make_float2(v0, v1);
            }
        }
    }
}

// ---------------- generic 16-output projection ----------------
__global__ __launch_bounds__(256) void proj16g(
    const float* __restrict__ Wm, int ldw,
    const float* __restrict__ bias,
    const float* __restrict__ X, int K, int hw,
    float* __restrict__ Y, int accum)
{
    __shared__ float Ws[16 * 256];
    const int b = blockIdx.y;
    const int p = blockIdx.x * 256 + threadIdx.x;
    for (int i = threadIdx.x; i < 16 * K; i += 256)
        Ws[i] = Wm[(i / K) * ldw + (i % K)];
    __syncthreads();
    float* Yp = Y + (size_t)b * 16 * hw + p;
    float acc[16];
#pragma unroll
    for (int o = 0; o < 16; o++)
        acc[o] = accum ? Yp[(size_t)o * hw] : (bias ? bias[o] : 0.0f);
    const float* Xp = X + (size_t)b * K * hw + p;
#pragma unroll 4
    for (int i = 0; i < K; i++) {
        float xv = Xp[(size_t)i * hw];
#pragma unroll
        for (int o = 0; o < 16; o++) acc[o] += Ws[o * K + i] * xv;
    }
#pragma unroll
    for (int o = 0; o < 16; o++) Yp[(size_t)o * hw] = acc[o];
}

// ---------------- split-K 16-output projection (K=256, accumulates) ----------------
__global__ __launch_bounds__(256) void proj16_splitk(
    const float* __restrict__ Wm, int ldw,
    const float* __restrict__ X,
    float* __restrict__ Y)
{
    __shared__ float Wsh[2][16 * 128];
    __shared__ float part[128][17];
    const int b  = blockIdx.y;
    const int px0 = blockIdx.x * 128;
    const int tid = threadIdx.x;
    const int pi = tid & 127;
    const int kh = tid >> 7;

    for (int i = tid; i < 4096; i += 256) {
        int o = i >> 8, k = i & 255;
        Wsh[k >> 7][o * 128 + (k & 127)] = Wm[o * ldw + k];
    }
    __syncthreads();

    float acc[16] = {};
    const float* Xp = X + ((size_t)b * 256 + kh * 128) * HWSZ + px0 + pi;
    const float* Wk = Wsh[kh];
#pragma unroll 4
    for (int i = 0; i < 128; i++) {
        float xv = Xp[(size_t)i * HWSZ];
#pragma unroll
        for (int o = 0; o < 16; o++) acc[o] += Wk[o * 128 + i] * xv;
    }

    if (kh == 1) {
#pragma unroll
        for (int o = 0; o < 16; o++) part[pi][o] = acc[o];
    }
    __syncthreads();
    if (kh == 0) {
        float* Yp = Y + (size_t)b * 16 * HWSZ + px0 + pi;
#pragma unroll
        for (int o = 0; o < 16; o++)
            Yp[(size_t)o * HWSZ] += acc[o] + part[pi][o];
    }
}

// ---------------- criss-cross logits (raw, R9-measured) ----------------
__global__ __launch_bounds__(256) void eH_kernel(const float* __restrict__ pq,
                                                 const float* __restrict__ pk,
                                                 float* __restrict__ att)
{
    __shared__ float PQ[16][128];
    __shared__ float PK[16][128];
    const int w = blockIdx.x, b = blockIdx.y;
    for (int i = threadIdx.x; i < 2048; i += 256) {
        int c = i >> 7, h = i & 127;
        size_t idx = (((size_t)b * 16 + c) * 128 + h) * 128 + w;
        PQ[c][h] = pq[idx];
        PK[c][h] = pk[idx];
    }
    __syncthreads();
    const int x  = threadIdx.x & 127;
    const int h0 = threadIdx.x >> 7;
    for (int h = h0; h < 128; h += 2) {
        float s = 0.0f;
#pragma unroll
        for (int c = 0; c < 16; c++) s += PQ[c][h] * PK[c][x];
        if (h == x) s += NEGINF;
        att[(((size_t)b * 128 + h) * 128 + w) * 256 + x] = s;
    }
}

__global__ __launch_bounds__(256) void eW_kernel(const float* __restrict__ pq,
                                                 const float* __restrict__ pk,
                                                 float* __restrict__ att)
{
    __shared__ float PQ[16][128];
    __shared__ float PK[16][128];
    const int h = blockIdx.x, b = blockIdx.y;
    for (int i = threadIdx.x; i < 2048; i += 256) {
        int c = i >> 7, w = i & 127;
        size_t idx = (((size_t)b * 16 + c) * 128 + h) * 128 + w;
        PQ[c][w] = pq[idx];
        PK[c][w] = pk[idx];
    }
    __syncthreads();
    const int x  = threadIdx.x & 127;
    const int w0 = threadIdx.x >> 7;
    for (int w = w0; w < 128; w += 2) {
        float s = 0.0f;
#pragma unroll
        for (int c = 0; c < 16; c++) s += PQ[c][w] * PK[c][x];
        att[(((size_t)b * 128 + h) * 128 + w) * 256 + 128 + x] = s;
    }
}

// ---------------- rowstat: per (b,h,w) row of 256 logits -> max, 1/sum(exp) ----------
__global__ __launch_bounds__(256) void rowstat_kernel(const float* __restrict__ att,
                                                      float* __restrict__ mrow,
                                                      float* __restrict__ irow)
{
    const int warp = threadIdx.x >> 5;
    const int lane = threadIdx.x & 31;
    const size_t row = (size_t)blockIdx.x * 8 + warp;
    const float* r = att + row * 256;
    float v[8];
    float mx = -INFINITY;
#pragma unroll
    for (int j = 0; j < 8; j++) { v[j] = r[lane + 32 * j]; mx = fmaxf(mx, v[j]); }
#pragma unroll
    for (int o = 16; o; o >>= 1) mx = fmaxf(mx, __shfl_xor_sync(0xffffffffu, mx, o));
    float s = 0.0f;
#pragma unroll
    for (int j = 0; j < 8; j++) s += __expf(v[j] - mx);
#pragma unroll
    for (int o = 16; o; o >>= 1) s += __shfl_xor_sync(0xffffffffu, s, o);
    if (lane == 0) {
        mrow[row] = mx;
        irow[row] = 1.0f / s;
    }
}

// ---------------- aggH: tmp[b,c,h,w] = inv[h,w]*sum_x pv[b,c,x,w]*exp(attH-m) ----------
__global__ __launch_bounds__(256) void aggH_mma(const float* __restrict__ pv,
                                                const float* __restrict__ att,
                                                const float* __restrict__ mrow,
                                                const float* __restrict__ irow,
                                                float* __restrict__ tmp)
{
    __shared__ unsigned As[16][136];
    __shared__ unsigned Bs[16][136];
    __shared__ float invs[128];
    const int w = blockIdx.x, b = blockIdx.y;
    const int tid  = threadIdx.x;
    const int warp = tid >> 5;
    const int lane = tid & 31;
    const int mbase = (warp >> 2) * 64;
    const int nbase = (warp & 3) * 32;

    const int cm = tid >> 1;
    const int xq = (tid & 1) * 8;

    if (tid < 128)
        invs[tid] = irow[((size_t)b * 128 + tid) * 128 + w];
    const float mr = mrow[((size_t)b * 128 + cm) * 128 + w];   // row for B staging (h=cm)

    float acc[4][4][4] = {};
    const float* pvp = pv + ((size_t)b * 128 + cm) * HWSZ + w;
    const float* atp = att + (((size_t)b * 128 + cm) * 128 + w) * 256;

    for (int k0 = 0; k0 < 128; k0 += 16) {
        float av[8];
#pragma unroll
        for (int j = 0; j < 8; j++) av[j] = pvp[(size_t)(k0 + xq + j) * 128];
        float4 b0 = *(const float4*)(atp + k0 + xq);
        float4 b1 = *(const float4*)(atp + k0 + xq + 4);

        __syncthreads();
#pragma unroll
        for (int j = 0; j < 8; j++) As[xq + j][cm] = f2tf(av[j]);
        Bs[xq + 0][cm] = f2tf(__expf(b0.x - mr));
        Bs[xq + 1][cm] = f2tf(__expf(b0.y - mr));
        Bs[xq + 2][cm] = f2tf(__expf(b0.z - mr));
        Bs[xq + 3][cm] = f2tf(__expf(b0.w - mr));
        Bs[xq + 4][cm] = f2tf(__expf(b1.x - mr));
        Bs[xq + 5][cm] = f2tf(__expf(b1.y - mr));
        Bs[xq + 6][cm] = f2tf(__expf(b1.z - mr));
        Bs[xq + 7][cm] = f2tf(__expf(b1.w - mr));
        __syncthreads();

        tile_mma(As, Bs, acc, lane, mbase, nbase);
    }

#pragma unroll
    for (int mt = 0; mt < 4; mt++)
#pragma unroll
        for (int half = 0; half < 2; half++) {
            int c = mbase + mt * 16 + (lane >> 2) + half * 8;
            size_t cb = ((size_t)b * 128 + c) * HWSZ + w;
#pragma unroll
            for (int nt = 0; nt < 4; nt++) {
                int h = nbase + nt * 8 + 2 * (lane & 3);
                tmp[cb + (size_t)h * 128]       = acc[mt][nt][half * 2 + 0] * invs[h];
                tmp[cb + (size_t)(h + 1) * 128] = acc[mt][nt][half * 2 + 1] * invs[h + 1];
            }
        }
}

// ---------------- aggW + update: value += gamma*(tmp + inv[h,w]*sum_x pv*exp(attW-m)) --
__global__ __launch_bounds__(256) void aggW_mma(const float* __restrict__ pv,
                                                const float* __restrict__ att,
                                                const float* __restrict__ mrow,
                                                const float* __restrict__ irow,
                                                const float* __restrict__ tmp,
                                                float* __restrict__ value,
                                                const float* __restrict__ gamma_p)
{
    __shared__ unsigned As[16][136];
    __shared__ unsigned Bs[16][136];
    __shared__ float invs[128];
    const int h = blockIdx.x, b = blockIdx.y;
    const int tid  = threadIdx.x;
    const int warp = tid >> 5;
    const int lane = tid & 31;
    const int mbase = (warp >> 2) * 64;
    const int nbase = (warp & 3) * 32;

    const int cm = tid >> 1;
    const int xq = (tid & 1) * 8;

    if (tid < 128)
        invs[tid] = irow[((size_t)b * 128 + h) * 128 + tid];
    const float mr = mrow[((size_t)b * 128 + h) * 128 + cm];   // row for B staging (w=cm)

    float acc[4][4][4] = {};
    const float* pvp = pv + (((size_t)b * 128 + cm) * 128 + h) * 128;
    const float* atp = att + (((size_t)b * 128 + h) * 128 + cm) * 256 + 128;

    for (int k0 = 0; k0 < 128; k0 += 16) {
        float4 a0 = *(const float4*)(pvp + k0 + xq);
        float4 a1 = *(const float4*)(pvp + k0 + xq + 4);
        float4 b0 = *(const float4*)(atp + k0 + xq);
        float4 b1 = *(const float4*)(atp + k0 + xq + 4);

        __syncthreads();
        As[xq + 0][cm] = f2tf(a0.x);
        As[xq + 1][cm] = f2tf(a0.y);
        As[xq + 2][cm] = f2tf(a0.z);
        As[xq + 3][cm] = f2tf(a0.w);
        As[xq + 4][cm] = f2tf(a1.x);
        As[xq + 5][cm] = f2tf(a1.y);
        As[xq + 6][cm] = f2tf(a1.z);
        As[xq + 7][cm] = f2tf(a1.w);
        Bs[xq + 0][cm] = f2tf(__expf(b0.x - mr));
        Bs[xq + 1][cm] = f2tf(__expf(b0.y - mr));
        Bs[xq + 2][cm] = f2tf(__expf(b0.z - mr));
        Bs[xq + 3][cm] = f2tf(__expf(b0.w - mr));
        Bs[xq + 4][cm] = f2tf(__expf(b1.x - mr));
        Bs[xq + 5][cm] = f2tf(__expf(b1.y - mr));
        Bs[xq + 6][cm] = f2tf(__expf(b1.z - mr));
        Bs[xq + 7][cm] = f2tf(__expf(b1.w - mr));
        __syncthreads();

        tile_mma(As, Bs, acc, lane, mbase, nbase);
    }

    const float g = *gamma_p;
#pragma unroll
    for (int mt = 0; mt < 4; mt++)
#pragma unroll
        for (int half = 0; half < 2; half++) {
            int c = mbase + mt * 16 + (lane >> 2) + half * 8;
            size_t rowb = (((size_t)b * 128 + c) * 128 + h) * 128;
#pragma unroll
            for (int nt = 0; nt < 4; nt++) {
                int n = nbase + nt * 8 + 2 * (lane & 3);
                float2 t = *(const float2*)(tmp + rowb + n);
                float2 v = *(const float2*)(value + rowb + n);
                v.x += g * (t.x + acc[mt][nt][half * 2 + 0] * invs[n]);
                v.y += g * (t.y + acc[mt][nt][half * 2 + 1] * invs[n + 1]);
                *(float2*)(value + rowb + n) = v;
            }
        }
}

// ---------------- launch ----------------
extern "C" void kernel_launch(void* const* d_in, const int* in_sizes, int n_in,
                              void* d_out, int out_size)
{
    const float* low   = (const float*)d_in[0];
    const float* high  = (const float*)d_in[1];
    const float* Wc1   = (const float*)d_in[2];
    const float* bc1   = (const float*)d_in[3];
    const float* Wc2   = (const float*)d_in[4];
    const float* bc2   = (const float*)d_in[5];
    const float* Wq    = (const float*)d_in[6];
    const float* bq    = (const float*)d_in[7];
    const float* Wk    = (const float*)d_in[8];
    const float* bk    = (const float*)d_in[9];
    const float* Wv    = (const float*)d_in[10];
    const float* bv    = (const float*)d_in[11];
    const float* gamma = (const float*)d_in[12];
    const float* Wb    = (const float*)d_in[13];
    const float* bng   = (const float*)d_in[14];
    const float* bnb   = (const float*)d_in[15];
    const float* bnm   = (const float*)d_in[16];
    const float* bnv   = (const float*)d_in[17];
    float* out = (float*)d_out;

    float *fbu, *value, *pv, *tmp, *pq, *pk, *att, *pqs, *vs, *fbs, *weff, *beff, *mrow, *irow;
    cudaGetSymbolAddress((void**)&fbu,   g_fbu);
    cudaGetSymbolAddress((void**)&value, g_value);
    cudaGetSymbolAddress((void**)&pv,    g_pv);
    cudaGetSymbolAddress((void**)&tmp,   g_tmp);
    cudaGetSymbolAddress((void**)&pq,    g_pq);
    cudaGetSymbolAddress((void**)&pk,    g_pk);
    cudaGetSymbolAddress((void**)&att,   g_att);
    cudaGetSymbolAddress((void**)&pqs,   g_pqs);
    cudaGetSymbolAddress((void**)&vs,    g_vs);
    cudaGetSymbolAddress((void**)&fbs,   g_fbs);
    cudaGetSymbolAddress((void**)&weff,  g_weff);
    cudaGetSymbolAddress((void**)&beff,  g_beff);
    cudaGetSymbolAddress((void**)&mrow,  g_mrow);
    cudaGetSymbolAddress((void**)&irow,  g_irow);

    // 0. fold Wq through Wc1 (query tensor never materialized)
    prep_weff<<<33, 256>>>(Wq, Wc1, bq, bc1, weff, beff);

    // 1. pq = upsample(Wq_eff_hi @ high) + Wq_eff_lo @ low
    proj16g<<<dim3(16, BB), 256>>>(weff, 512, beff, high, 256, 4096, pqs, 0);
    upsample_kernel<<<4096, 256>>>(pqs, pq);
    proj16_splitk<<<dim3(128, BB), 256>>>(weff + 256, 512, low, pq);

    // 2. value = upsample(Wc2 @ high + bc2)
    gemm_dual<<<dim3(32, 1, BB), 256>>>(Wc2, 256, bc2, high, 256, vs, 128, 4096,
                                        nullptr, nullptr, nullptr, nullptr, nullptr);
    upsample_kernel<<<32768, 256>>>(vs, value);

    // 3. fbu = upsample(Wb[:,128:] @ high)
    gemm_dual<<<dim3(32, 2, BB), 256>>>(Wb + 128, 384, nullptr, high, 256, fbs, 256, 4096,
                                        nullptr, nullptr, nullptr, nullptr, nullptr);
    upsample_kernel<<<65536, 256>>>(fbs, fbu);

    // 4. two criss-cross attention iterations (softmax -> rowstat + exp-in-staging)
    for (int it = 0; it < 2; it++) {
        proj16g<<<dim3(64, BB), 256>>>(Wk, 128, bk, value, 128, HWSZ, pk, 0);
        gemm_dual<<<dim3(128, 1, BB), 256>>>(Wv, 128, bv, value, 128, pv, 128, HWSZ,
                                             nullptr, nullptr, nullptr, nullptr, nullptr);
        eH_kernel<<<dim3(128, BB), 256>>>(pq, pk, att);
        eW_kernel<<<dim3(128, BB), 256>>>(pq, pk, att);
        rowstat_kernel<<<8192, 256>>>(att, mrow, irow);
        aggH_mma<<<dim3(128, BB), 256>>>(pv, att, mrow, irow, tmp);
        aggW_mma<<<dim3(128, BB), 256>>>(pv, att, mrow, irow, tmp, value, gamma);
    }

    // 5. out = ReLU(BN(Wb[:,:128] @ value + fbu))
    gemm_dual<<<dim3(128, 2, BB), 256>>>(Wb, 384, nullptr, value, 128, out, 256, HWSZ,
                                         fbu, bng, bnb, bnm, bnv);
}

// round 12
// speedup vs baseline: 1.0898x; 1.0210x over previous
#include <cuda_runtime.h>
#include <math.h>

#define BB   4
#define HWSZ 16384        // 128*128
#define NEGINF (-1000000000.0f)

// ---------------- scratch (device globals: no allocation allowed) ----------------
__device__ float g_fbu  [16777216];  // upsampled Wb_hi@high (4,256,128,128)
__device__ float g_value[ 8388608];  // (4,128,128,128)
__device__ float g_pv   [ 8388608];
__device__ float g_tmp  [ 8388608];
__device__ float g_pq   [ 1048576];  // (4,16,128,128)
__device__ float g_pk   [ 1048576];
__device__ float g_att  [16777216];  // (4,128,128,256) raw logits
__device__ float g_pqs  [  262144];  // (4,16,64,64)
__device__ float g_vs   [ 2097152];  // (4,128,64,64)
__device__ float g_fbs  [ 4194304];  // (4,256,64,64)
__device__ float g_weff [    8192];  // Wq@Wc1 (16,512)
__device__ float g_beff [      16];
__device__ float g_mrow [   65536];  // per-row max
__device__ float g_irow [   65536];  // per-row 1/sum

// ---------------- tf32 helpers ----------------
__device__ __forceinline__ unsigned f2tf(float f) {
    unsigned r;
    asm("cvt.rna.tf32.f32 %0, %1;" : "=r"(r) : "f"(f));
    return r;
}

__device__ __forceinline__ void mma8(float* d, const unsigned* a, const unsigned* b) {
    asm("mma.sync.aligned.m16n8k8.row.col.f32.tf32.tf32.f32 "
        "{%0,%1,%2,%3},{%4,%5,%6,%7},{%8,%9},{%0,%1,%2,%3};"
        : "+f"(d[0]), "+f"(d[1]), "+f"(d[2]), "+f"(d[3])
        : "r"(a[0]), "r"(a[1]), "r"(a[2]), "r"(a[3]), "r"(b[0]), "r"(b[1]));
}

__device__ __forceinline__ void tile_mma(const unsigned (*As)[136],
                                         const unsigned (*Bs)[136],
                                         float acc[4][4][4],
                                         int lane, int mbase, int nbase)
{
#pragma unroll
    for (int kt = 0; kt < 2; kt++) {
        unsigned a[4][4], b[4][2];
        const int kb = kt * 8 + (lane & 3);
        const int rq = lane >> 2;
#pragma unroll
        for (int mt = 0; mt < 4; mt++) {
            int m = mbase + mt * 16 + rq;
            a[mt][0] = As[kb][m];
            a[mt][1] = As[kb][m + 8];
            a[mt][2] = As[kb + 4][m];
            a[mt][3] = As[kb + 4][m + 8];
        }
#pragma unroll
        for (int nt = 0; nt < 4; nt++) {
            int n = nbase + nt * 8 + rq;
            b[nt][0] = Bs[kb][n];
            b[nt][1] = Bs[kb + 4][n];
        }
#pragma unroll
        for (int mt = 0; mt < 4; mt++)
#pragma unroll
            for (int nt = 0; nt < 4; nt++)
                mma8(acc[mt][nt], a[mt], b[nt]);
    }
}

// ---------------- Wq_eff = Wq @ Wc1 ; b_eff = bq + Wq @ bc1 ----------------
__global__ __launch_bounds__(256) void prep_weff(
    const float* __restrict__ Wq, const float* __restrict__ Wc1,
    const float* __restrict__ bq, const float* __restrict__ bc1,
    float* __restrict__ weff, float* __restrict__ beff)
{
    int t = blockIdx.x * 256 + threadIdx.x;
    if (blockIdx.x < 32) {
        int o = t >> 9, j = t & 511;
        float s = 0.0f;
#pragma unroll 4
        for (int i = 0; i < 128; i++) s += Wq[o * 128 + i] * Wc1[i * 512 + j];
        weff[o * 512 + j] = s;
    } else if (threadIdx.x < 16) {
        int o = threadIdx.x;
        float s = bq[o];
        for (int i = 0; i < 128; i++) s += Wq[o * 128 + i] * bc1[i];
        beff[o] = s;
    }
}

// ---------------- bilinear 2x upsample ----------------
__global__ __launch_bounds__(256) void upsample_kernel(const float* __restrict__ in,
                                                       float* __restrict__ out) {
    int idx = blockIdx.x * 256 + threadIdx.x;
    int ox = idx & 127;
    int oy = (idx >> 7) & 127;
    int bc = idx >> 14;
    float fy = 0.5f * oy - 0.25f;
    float fx = 0.5f * ox - 0.25f;
    int y0 = (int)floorf(fy); float wy = fy - (float)y0;
    int x0 = (int)floorf(fx); float wx = fx - (float)x0;
    int y1 = min(y0 + 1, 63); y0 = max(y0, 0);
    int x1 = min(x0 + 1, 63); x0 = max(x0, 0);
    const float* p = in + (size_t)bc * 4096;
    float v00 = p[y0 * 64 + x0], v01 = p[y0 * 64 + x1];
    float v10 = p[y1 * 64 + x0], v11 = p[y1 * 64 + x1];
    float top = v00 + wx * (v01 - v00);
    float bot = v10 + wx * (v11 - v10);
    out[idx] = top + wy * (bot - top);
}

// ---------------- tf32 GEMM with register-prefetch pipelining ----------------
__global__ __launch_bounds__(256) void gemm_dual(
    const float* __restrict__ Wm, int ldw,
    const float* __restrict__ bias,
    const float* __restrict__ X, int I,
    float* __restrict__ Y, int O, int hw,
    const float* __restrict__ addin,
    const float* __restrict__ bng, const float* __restrict__ bnb,
    const float* __restrict__ bnm, const float* __restrict__ bnv)
{
    __shared__ unsigned As[16][136];
    __shared__ unsigned Bs[16][136];
    const int b  = blockIdx.z;
    const int to = blockIdx.y * 128;
    const int tp = blockIdx.x * 128;
    const int tid  = threadIdx.x;
    const int warp = tid >> 5;
    const int lane = tid & 31;
    const int mbase = (warp >> 2) * 64;
    const int nbase = (warp & 3) * 32;

    const int am  = tid >> 1;
    const int akq = (tid & 1) * 8;
    const int bk  = tid >> 4;
    const int bn  = (tid & 15) * 8;

    const float* Xp0 = X + (size_t)b * I * hw + tp + bn;
    const int nK = I >> 4;

    float acc[4][4][4] = {};
    float4 w0, w1, x0, x1;

    auto loadG = [&](int k0) {
        const float* Wp = Wm + (size_t)(to + am) * ldw + k0 + akq;
        w0 = *(const float4*)Wp;
        w1 = *(const float4*)(Wp + 4);
        const float* Xp = Xp0 + (size_t)(k0 + bk) * hw;
        x0 = *(const float4*)Xp;
        x1 = *(const float4*)(Xp + 4);
    };
    auto storeS = [&]() {
        As[akq + 0][am] = f2tf(w0.x);
        As[akq + 1][am] = f2tf(w0.y);
        As[akq + 2][am] = f2tf(w0.z);
        As[akq + 3][am] = f2tf(w0.w);
        As[akq + 4][am] = f2tf(w1.x);
        As[akq + 5][am] = f2tf(w1.y);
        As[akq + 6][am] = f2tf(w1.z);
        As[akq + 7][am] = f2tf(w1.w);
        *(uint4*)&Bs[bk][bn]     = make_uint4(f2tf(x0.x), f2tf(x0.y), f2tf(x0.z), f2tf(x0.w));
        *(uint4*)&Bs[bk][bn + 4] = make_uint4(f2tf(x1.x), f2tf(x1.y), f2tf(x1.z), f2tf(x1.w));
    };

    loadG(0);
    for (int kt = 0; kt < nK; kt++) {
        __syncthreads();   // protect smem from previous mma readers
        storeS();
        __syncthreads();
        if (kt + 1 < nK) loadG((kt + 1) << 4);   // loads fly during mma below
        tile_mma(As, Bs, acc, lane, mbase, nbase);
    }

    const bool dobn = (bng != nullptr);
#pragma unroll
    for (int mt = 0; mt < 4; mt++) {
#pragma unroll
        for (int half = 0; half < 2; half++) {
            int o = to + mbase + mt * 16 + (lane >> 2) + half * 8;
            float bia = bias ? bias[o] : 0.0f;
            float sc = 1.0f, mn = 0.0f, bt = 0.0f;
            if (dobn) {
                sc = bng[o] * rsqrtf(bnv[o] + 1e-5f);
                mn = bnm[o];
                bt = bnb[o];
            }
            size_t rowb = ((size_t)b * O + o) * hw + tp;
#pragma unroll
            for (int nt = 0; nt < 4; nt++) {
                int n = nbase + nt * 8 + 2 * (lane & 3);
                float v0 = acc[mt][nt][half * 2 + 0] + bia;
                float v1 = acc[mt][nt][half * 2 + 1] + bia;
                if (addin) {
                    float2 ad = *(const float2*)(addin + rowb + n);
                    v0 += ad.x; v1 += ad.y;
                }
                if (dobn) {
                    v0 = fmaxf((v0 - mn) * sc + bt, 0.0f);
                    v1 = fmaxf((v1 - mn) * sc + bt, 0.0f);
                }
                *(float2*)(Y + rowb + n) = make_float2(v0, v1);
            }
        }
    }
}

// ---------------- generic 16-output projection ----------------
__global__ __launch_bounds__(256) void proj16g(
    const float* __restrict__ Wm, int ldw,
    const float* __restrict__ bias,
    const float* __restrict__ X, int K, int hw,
    float* __restrict__ Y, int accum)
{
    __shared__ float Ws[16 * 256];
    const int b = blockIdx.y;
    const int p = blockIdx.x * 256 + threadIdx.x;
    for (int i = threadIdx.x; i < 16 * K; i += 256)
        Ws[i] = Wm[(i / K) * ldw + (i % K)];
    __syncthreads();
    float* Yp = Y + (size_t)b * 16 * hw + p;
    float acc[16];
#pragma unroll
    for (int o = 0; o < 16; o++)
        acc[o] = accum ? Yp[(size_t)o * hw] : (bias ? bias[o] : 0.0f);
    const float* Xp = X + (size_t)b * K * hw + p;
#pragma unroll 4
    for (int i = 0; i < K; i++) {
        float xv = Xp[(size_t)i * hw];
#pragma unroll
        for (int o = 0; o < 16; o++) acc[o] += Ws[o * K + i] * xv;
    }
#pragma unroll
    for (int o = 0; o < 16; o++) Yp[(size_t)o * hw] = acc[o];
}

// ---------------- 4-way split-K 16-output projection (K=256, accumulates) ------------
// 64 pixels/block, 4 k-groups of 64 channels each.
__global__ __launch_bounds__(256) void proj16_splitk(
    const float* __restrict__ Wm, int ldw,
    const float* __restrict__ X,
    float* __restrict__ Y)
{
    __shared__ float Wsh[16 * 256];          // [o*256 + k] full weights
    __shared__ float part[3][64][17];
    const int b  = blockIdx.y;
    const int px0 = blockIdx.x * 64;
    const int tid = threadIdx.x;
    const int pi = tid & 63;
    const int kg = tid >> 6;                 // 0..3

    for (int i = tid; i < 4096; i += 256)
        Wsh[i] = Wm[(i >> 8) * ldw + (i & 255)];
    __syncthreads();

    float acc[16] = {};
    const float* Xp = X + ((size_t)b * 256 + kg * 64) * HWSZ + px0 + pi;
    const float* Wk = Wsh + kg * 64;
#pragma unroll 4
    for (int i = 0; i < 64; i++) {
        float xv = Xp[(size_t)i * HWSZ];
#pragma unroll
        for (int o = 0; o < 16; o++) acc[o] += Wk[o * 256 + i] * xv;
    }

    if (kg > 0) {
#pragma unroll
        for (int o = 0; o < 16; o++) part[kg - 1][pi][o] = acc[o];
    }
    __syncthreads();
    if (kg == 0) {
        float* Yp = Y + (size_t)b * 16 * HWSZ + px0 + pi;
#pragma unroll
        for (int o = 0; o < 16; o++)
            Yp[(size_t)o * HWSZ] += acc[o] + part[0][pi][o] + part[1][pi][o] + part[2][pi][o];
    }
}

// ---------------- criss-cross logits (raw, R9-measured) ----------------
__global__ __launch_bounds__(256) void eH_kernel(const float* __restrict__ pq,
                                                 const float* __restrict__ pk,
                                                 float* __restrict__ att)
{
    __shared__ float PQ[16][128];
    __shared__ float PK[16][128];
    const int w = blockIdx.x, b = blockIdx.y;
    for (int i = threadIdx.x; i < 2048; i += 256) {
        int c = i >> 7, h = i & 127;
        size_t idx = (((size_t)b * 16 + c) * 128 + h) * 128 + w;
        PQ[c][h] = pq[idx];
        PK[c][h] = pk[idx];
    }
    __syncthreads();
    const int x  = threadIdx.x & 127;
    const int h0 = threadIdx.x >> 7;
    for (int h = h0; h < 128; h += 2) {
        float s = 0.0f;
#pragma unroll
        for (int c = 0; c < 16; c++) s += PQ[c][h] * PK[c][x];
        if (h == x) s += NEGINF;
        att[(((size_t)b * 128 + h) * 128 + w) * 256 + x] = s;
    }
}

__global__ __launch_bounds__(256) void eW_kernel(const float* __restrict__ pq,
                                                 const float* __restrict__ pk,
                                                 float* __restrict__ att)
{
    __shared__ float PQ[16][128];
    __shared__ float PK[16][128];
    const int h = blockIdx.x, b = blockIdx.y;
    for (int i = threadIdx.x; i < 2048; i += 256) {
        int c = i >> 7, w = i & 127;
        size_t idx = (((size_t)b * 16 + c) * 128 + h) * 128 + w;
        PQ[c][w] = pq[idx];
        PK[c][w] = pk[idx];
    }
    __syncthreads();
    const int x  = threadIdx.x & 127;
    const int w0 = threadIdx.x >> 7;
    for (int w = w0; w < 128; w += 2) {
        float s = 0.0f;
#pragma unroll
        for (int c = 0; c < 16; c++) s += PQ[c][w] * PK[c][x];
        att[(((size_t)b * 128 + h) * 128 + w) * 256 + 128 + x] = s;
    }
}

// ---------------- rowstat: per (b,h,w) row of 256 logits -> max, 1/sum(exp) ----------
__global__ __launch_bounds__(256) void rowstat_kernel(const float* __restrict__ att,
                                                      float* __restrict__ mrow,
                                                      float* __restrict__ irow)
{
    const int warp = threadIdx.x >> 5;
    const int lane = threadIdx.x & 31;
    const size_t row = (size_t)blockIdx.x * 8 + warp;
    const float* r = att + row * 256;
    float v[8];
    float mx = -INFINITY;
#pragma unroll
    for (int j = 0; j < 8; j++) { v[j] = r[lane + 32 * j]; mx = fmaxf(mx, v[j]); }
#pragma unroll
    for (int o = 16; o; o >>= 1) mx = fmaxf(mx, __shfl_xor_sync(0xffffffffu, mx, o));
    float s = 0.0f;
#pragma unroll
    for (int j = 0; j < 8; j++) s += __expf(v[j] - mx);
#pragma unroll
    for (int o = 16; o; o >>= 1) s += __shfl_xor_sync(0xffffffffu, s, o);
    if (lane == 0) {
        mrow[row] = mx;
        irow[row] = 1.0f / s;
    }
}

// ---------------- aggH (register-prefetch pipelined) ----------------
__global__ __launch_bounds__(256) void aggH_mma(const float* __restrict__ pv,
                                                const float* __restrict__ att,
                                                const float* __restrict__ mrow,
                                                const float* __restrict__ irow,
                                                float* __restrict__ tmp)
{
    __shared__ unsigned As[16][136];
    __shared__ unsigned Bs[16][136];
    __shared__ float invs[128];
    const int w = blockIdx.x, b = blockIdx.y;
    const int tid  = threadIdx.x;
    const int warp = tid >> 5;
    const int lane = tid & 31;
    const int mbase = (warp >> 2) * 64;
    const int nbase = (warp & 3) * 32;

    const int cm = tid >> 1;
    const int xq = (tid & 1) * 8;

    if (tid < 128)
        invs[tid] = irow[((size_t)b * 128 + tid) * 128 + w];
    const float mr = mrow[((size_t)b * 128 + cm) * 128 + w];

    float acc[4][4][4] = {};
    const float* pvp = pv + ((size_t)b * 128 + cm) * HWSZ + w;
    const float* atp = att + (((size_t)b * 128 + cm) * 128 + w) * 256;

    float av[8];
    float4 b0, b1;
    auto loadG = [&](int k0) {
#pragma unroll
        for (int j = 0; j < 8; j++) av[j] = pvp[(size_t)(k0 + xq + j) * 128];
        b0 = *(const float4*)(atp + k0 + xq);
        b1 = *(const float4*)(atp + k0 + xq + 4);
    };
    auto storeS = [&]() {
#pragma unroll
        for (int j = 0; j < 8; j++) As[xq + j][cm] = f2tf(av[j]);
        Bs[xq + 0][cm] = f2tf(__expf(b0.x - mr));
        Bs[xq + 1][cm] = f2tf(__expf(b0.y - mr));
        Bs[xq + 2][cm] = f2tf(__expf(b0.z - mr));
        Bs[xq + 3][cm] = f2tf(__expf(b0.w - mr));
        Bs[xq + 4][cm] = f2tf(__expf(b1.x - mr));
        Bs[xq + 5][cm] = f2tf(__expf(b1.y - mr));
        Bs[xq + 6][cm] = f2tf(__expf(b1.z - mr));
        Bs[xq + 7][cm] = f2tf(__expf(b1.w - mr));
    };

    loadG(0);
    for (int kt = 0; kt < 8; kt++) {
        __syncthreads();
        storeS();
        __syncthreads();
        if (kt < 7) loadG((kt + 1) << 4);
        tile_mma(As, Bs, acc, lane, mbase, nbase);
    }

#pragma unroll
    for (int mt = 0; mt < 4; mt++)
#pragma unroll
        for (int half = 0; half < 2; half++) {
            int c = mbase + mt * 16 + (lane >> 2) + half * 8;
            size_t cb = ((size_t)b * 128 + c) * HWSZ + w;
#pragma unroll
            for (int nt = 0; nt < 4; nt++) {
                int h = nbase + nt * 8 + 2 * (lane & 3);
                tmp[cb + (size_t)h * 128]       = acc[mt][nt][half * 2 + 0] * invs[h];
                tmp[cb + (size_t)(h + 1) * 128] = acc[mt][nt][half * 2 + 1] * invs[h + 1];
            }
        }
}

// ---------------- aggW + update (register-prefetch pipelined) ----------------
__global__ __launch_bounds__(256) void aggW_mma(const float* __restrict__ pv,
                                                const float* __restrict__ att,
                                                const float* __restrict__ mrow,
                                                const float* __restrict__ irow,
                                                const float* __restrict__ tmp,
                                                float* __restrict__ value,
                                                const float* __restrict__ gamma_p)
{
    __shared__ unsigned As[16][136];
    __shared__ unsigned Bs[16][136];
    __shared__ float invs[128];
    const int h = blockIdx.x, b = blockIdx.y;
    const int tid  = threadIdx.x;
    const int warp = tid >> 5;
    const int lane = tid & 31;
    const int mbase = (warp >> 2) * 64;
    const int nbase = (warp & 3) * 32;

    const int cm = tid >> 1;
    const int xq = (tid & 1) * 8;

    if (tid < 128)
        invs[tid] = irow[((size_t)b * 128 + h) * 128 + tid];
    const float mr = mrow[((size_t)b * 128 + h) * 128 + cm];

    float acc[4][4][4] = {};
    const float* pvp = pv + (((size_t)b * 128 + cm) * 128 + h) * 128;
    const float* atp = att + (((size_t)b * 128 + h) * 128 + cm) * 256 + 128;

    float4 a0, a1, b0, b1;
    auto loadG = [&](int k0) {
        a0 = *(const float4*)(pvp + k0 + xq);
        a1 = *(const float4*)(pvp + k0 + xq + 4);
        b0 = *(const float4*)(atp + k0 + xq);
        b1 = *(const float4*)(atp + k0 + xq + 4);
    };
    auto storeS = [&]() {
        As[xq + 0][cm] = f2tf(a0.x);
        As[xq + 1][cm] = f2tf(a0.y);
        As[xq + 2][cm] = f2tf(a0.z);
        As[xq + 3][cm] = f2tf(a0.w);
        As[xq + 4][cm] = f2tf(a1.x);
        As[xq + 5][cm] = f2tf(a1.y);
        As[xq + 6][cm] = f2tf(a1.z);
        As[xq + 7][cm] = f2tf(a1.w);
        Bs[xq + 0][cm] = f2tf(__expf(b0.x - mr));
        Bs[xq + 1][cm] = f2tf(__expf(b0.y - mr));
        Bs[xq + 2][cm] = f2tf(__expf(b0.z - mr));
        Bs[xq + 3][cm] = f2tf(__expf(b0.w - mr));
        Bs[xq + 4][cm] = f2tf(__expf(b1.x - mr));
        Bs[xq + 5][cm] = f2tf(__expf(b1.y - mr));
        Bs[xq + 6][cm] = f2tf(__expf(b1.z - mr));
        Bs[xq + 7][cm] = f2tf(__expf(b1.w - mr));
    };

    loadG(0);
    for (int kt = 0; kt < 8; kt++) {
        __syncthreads();
        storeS();
        __syncthreads();
        if (kt < 7) loadG((kt + 1) << 4);
        tile_mma(As, Bs, acc, lane, mbase, nbase);
    }

    const float g = *gamma_p;
#pragma unroll
    for (int mt = 0; mt < 4; mt++)
#pragma unroll
        for (int half = 0; half < 2; half++) {
            int c = mbase + mt * 16 + (lane >> 2) + half * 8;
            size_t rowb = (((size_t)b * 128 + c) * 128 + h) * 128;
#pragma unroll
            for (int nt = 0; nt < 4; nt++) {
                int n = nbase + nt * 8 + 2 * (lane & 3);
                float2 t = *(const float2*)(tmp + rowb + n);
                float2 v = *(const float2*)(value + rowb + n);
                v.x += g * (t.x + acc[mt][nt][half * 2 + 0] * invs[n]);
                v.y += g * (t.y + acc[mt][nt][half * 2 + 1] * invs[n + 1]);
                *(float2*)(value + rowb + n) = v;
            }
        }
}

// ---------------- launch ----------------
extern "C" void kernel_launch(void* const* d_in, const int* in_sizes, int n_in,
                              void* d_out, int out_size)
{
    const float* low   = (const float*)d_in[0];
    const float* high  = (const float*)d_in[1];
    const float* Wc1   = (const float*)d_in[2];
    const float* bc1   = (const float*)d_in[3];
    const float* Wc2   = (const float*)d_in[4];
    const float* bc2   = (const float*)d_in[5];
    const float* Wq    = (const float*)d_in[6];
    const float* bq    = (const float*)d_in[7];
    const float* Wk    = (const float*)d_in[8];
    const float* bk    = (const float*)d_in[9];
    const float* Wv    = (const float*)d_in[10];
    const float* bv    = (const float*)d_in[11];
    const float* gamma = (const float*)d_in[12];
    const float* Wb    = (const float*)d_in[13];
    const float* bng   = (const float*)d_in[14];
    const float* bnb   = (const float*)d_in[15];
    const float* bnm   = (const float*)d_in[16];
    const float* bnv   = (const float*)d_in[17];
    float* out = (float*)d_out;

    float *fbu, *value, *pv, *tmp, *pq, *pk, *att, *pqs, *vs, *fbs, *weff, *beff, *mrow, *irow;
    cudaGetSymbolAddress((void**)&fbu,   g_fbu);
    cudaGetSymbolAddress((void**)&value, g_value);
    cudaGetSymbolAddress((void**)&pv,    g_pv);
    cudaGetSymbolAddress((void**)&tmp,   g_tmp);
    cudaGetSymbolAddress((void**)&pq,    g_pq);
    cudaGetSymbolAddress((void**)&pk,    g_pk);
    cudaGetSymbolAddress((void**)&att,   g_att);
    cudaGetSymbolAddress((void**)&pqs,   g_pqs);
    cudaGetSymbolAddress((void**)&vs,    g_vs);
    cudaGetSymbolAddress((void**)&fbs,   g_fbs);
    cudaGetSymbolAddress((void**)&weff,  g_weff);
    cudaGetSymbolAddress((void**)&beff,  g_beff);
    cudaGetSymbolAddress((void**)&mrow,  g_mrow);
    cudaGetSymbolAddress((void**)&irow,  g_irow);

    // 0. fold Wq through Wc1 (query tensor never materialized)
    prep_weff<<<33, 256>>>(Wq, Wc1, bq, bc1, weff, beff);

    // 1. pq = upsample(Wq_eff_hi @ high) + Wq_eff_lo @ low
    proj16g<<<dim3(16, BB), 256>>>(weff, 512, beff, high, 256, 4096, pqs, 0);
    upsample_kernel<<<4096, 256>>>(pqs, pq);
    proj16_splitk<<<dim3(256, BB), 256>>>(weff + 256, 512, low, pq);

    // 2. value = upsample(Wc2 @ high + bc2)
    gemm_dual<<<dim3(32, 1, BB), 256>>>(Wc2, 256, bc2, high, 256, vs, 128, 4096,
                                        nullptr, nullptr, nullptr, nullptr, nullptr);
    upsample_kernel<<<32768, 256>>>(vs, value);

    // 3. fbu = upsample(Wb[:,128:] @ high)
    gemm_dual<<<dim3(32, 2, BB), 256>>>(Wb + 128, 384, nullptr, high, 256, fbs, 256, 4096,
                                        nullptr, nullptr, nullptr, nullptr, nullptr);
    upsample_kernel<<<65536, 256>>>(fbs, fbu);

    // 4. two criss-cross attention iterations
    for (int it = 0; it < 2; it++) {
        proj16g<<<dim3(64, BB), 256>>>(Wk, 128, bk, value, 128, HWSZ, pk, 0);
        gemm_dual<<<dim3(128, 1, BB), 256>>>(Wv, 128, bv, value, 128, pv, 128, HWSZ,
                                             nullptr, nullptr, nullptr, nullptr, nullptr);
        eH_kernel<<<dim3(128, BB), 256>>>(pq, pk, att);
        eW_kernel<<<dim3(128, BB), 256>>>(pq, pk, att);
        rowstat_kernel<<<8192, 256>>>(att, mrow, irow);
        aggH_mma<<<dim3(128, BB), 256>>>(pv, att, mrow, irow, tmp);
        aggW_mma<<<dim3(128, BB), 256>>>(pv, att, mrow, irow, tmp, value, gamma);
    }

    // 5. out = ReLU(BN(Wb[:,:128] @ value + fbu))
    gemm_dual<<<dim3(128, 2, BB), 256>>>(Wb, 384, nullptr, value, 128, out, 256, HWSZ,
                                         fbu, bng, bnb, bnm, bnv);
}

// round 13
// speedup vs baseline: 1.1312x; 1.0379x over previous
#include <cuda_runtime.h>
#include <math.h>

#define BB   4
#define HWSZ 16384        // 128*128
#define NEGINF (-1000000000.0f)

// ---------------- scratch (device globals: no allocation allowed) ----------------
__device__ float g_fbu  [16777216];  // upsampled Wb_hi@high (4,256,128,128)
__device__ float g_value[ 8388608];  // (4,128,128,128)
__device__ float g_pv   [ 8388608];
__device__ float g_tmp  [ 8388608];  // unnormalized U
__device__ float g_pq   [ 1048576];  // (4,16,128,128)
__device__ float g_pk   [ 1048576];
__device__ float g_att  [16777216];  // (4,128,128,256) raw logits
__device__ float g_pqs  [  262144];  // (4,16,64,64)
__device__ float g_vs   [ 2097152];  // (4,128,64,64)
__device__ float g_fbs  [ 4194304];  // (4,256,64,64)
__device__ float g_weff [    8192];  // Wq@Wc1 (16,512)
__device__ float g_beff [      16];
__device__ float g_sumH [   65536];  // (4,128,128) sum of exp over H-branch

// ---------------- tf32 helpers ----------------
__device__ __forceinline__ unsigned f2tf(float f) {
    unsigned r;
    asm("cvt.rna.tf32.f32 %0, %1;" : "=r"(r) : "f"(f));
    return r;
}

__device__ __forceinline__ void mma8(float* d, const unsigned* a, const unsigned* b) {
    asm("mma.sync.aligned.m16n8k8.row.col.f32.tf32.tf32.f32 "
        "{%0,%1,%2,%3},{%4,%5,%6,%7},{%8,%9},{%0,%1,%2,%3};"
        : "+f"(d[0]), "+f"(d[1]), "+f"(d[2]), "+f"(d[3])
        : "r"(a[0]), "r"(a[1]), "r"(a[2]), "r"(a[3]), "r"(b[0]), "r"(b[1]));
}

__device__ __forceinline__ void tile_mma(const unsigned (*As)[136],
                                         const unsigned (*Bs)[136],
                                         float acc[4][4][4],
                                         int lane, int mbase, int nbase)
{
#pragma unroll
    for (int kt = 0; kt < 2; kt++) {
        unsigned a[4][4], b[4][2];
        const int kb = kt * 8 + (lane & 3);
        const int rq = lane >> 2;
#pragma unroll
        for (int mt = 0; mt < 4; mt++) {
            int m = mbase + mt * 16 + rq;
            a[mt][0] = As[kb][m];
            a[mt][1] = As[kb][m + 8];
            a[mt][2] = As[kb + 4][m];
            a[mt][3] = As[kb + 4][m + 8];
        }
#pragma unroll
        for (int nt = 0; nt < 4; nt++) {
            int n = nbase + nt * 8 + rq;
            b[nt][0] = Bs[kb][n];
            b[nt][1] = Bs[kb + 4][n];
        }
#pragma unroll
        for (int mt = 0; mt < 4; mt++)
#pragma unroll
            for (int nt = 0; nt < 4; nt++)
                mma8(acc[mt][nt], a[mt], b[nt]);
    }
}

// ---------------- Wq_eff = Wq @ Wc1 ; b_eff = bq + Wq @ bc1 ----------------
__global__ __launch_bounds__(256) void prep_weff(
    const float* __restrict__ Wq, const float* __restrict__ Wc1,
    const float* __restrict__ bq, const float* __restrict__ bc1,
    float* __restrict__ weff, float* __restrict__ beff)
{
    int t = blockIdx.x * 256 + threadIdx.x;
    if (blockIdx.x < 32) {
        int o = t >> 9, j = t & 511;
        float s = 0.0f;
#pragma unroll 4
        for (int i = 0; i < 128; i++) s += Wq[o * 128 + i] * Wc1[i * 512 + j];
        weff[o * 512 + j] = s;
    } else if (threadIdx.x < 16) {
        int o = threadIdx.x;
        float s = bq[o];
        for (int i = 0; i < 128; i++) s += Wq[o * 128 + i] * bc1[i];
        beff[o] = s;
    }
}

// ---------------- bilinear 2x upsample ----------------
__global__ __launch_bounds__(256) void upsample_kernel(const float* __restrict__ in,
                                                       float* __restrict__ out) {
    int idx = blockIdx.x * 256 + threadIdx.x;
    int ox = idx & 127;
    int oy = (idx >> 7) & 127;
    int bc = idx >> 14;
    float fy = 0.5f * oy - 0.25f;
    float fx = 0.5f * ox - 0.25f;
    int y0 = (int)floorf(fy); float wy = fy - (float)y0;
    int x0 = (int)floorf(fx); float wx = fx - (float)x0;
    int y1 = min(y0 + 1, 63); y0 = max(y0, 0);
    int x1 = min(x0 + 1, 63); x0 = max(x0, 0);
    const float* p = in + (size_t)bc * 4096;
    float v00 = p[y0 * 64 + x0], v01 = p[y0 * 64 + x1];
    float v10 = p[y1 * 64 + x0], v11 = p[y1 * 64 + x1];
    float top = v00 + wx * (v01 - v00);
    float bot = v10 + wx * (v11 - v10);
    out[idx] = top + wy * (bot - top);
}

// ---------------- tf32 GEMM with register-prefetch pipelining ----------------
__global__ __launch_bounds__(256) void gemm_dual(
    const float* __restrict__ Wm, int ldw,
    const float* __restrict__ bias,
    const float* __restrict__ X, int I,
    float* __restrict__ Y, int O, int hw,
    const float* __restrict__ addin,
    const float* __restrict__ bng, const float* __restrict__ bnb,
    const float* __restrict__ bnm, const float* __restrict__ bnv)
{
    __shared__ unsigned As[16][136];
    __shared__ unsigned Bs[16][136];
    const int b  = blockIdx.z;
    const int to = blockIdx.y * 128;
    const int tp = blockIdx.x * 128;
    const int tid  = threadIdx.x;
    const int warp = tid >> 5;
    const int lane = tid & 31;
    const int mbase = (warp >> 2) * 64;
    const int nbase = (warp & 3) * 32;

    const int am  = tid >> 1;
    const int akq = (tid & 1) * 8;
    const int bk  = tid >> 4;
    const int bn  = (tid & 15) * 8;

    const float* Xp0 = X + (size_t)b * I * hw + tp + bn;
    const int nK = I >> 4;

    float acc[4][4][4] = {};
    float4 w0, w1, x0, x1;

    auto loadG = [&](int k0) {
        const float* Wp = Wm + (size_t)(to + am) * ldw + k0 + akq;
        w0 = *(const float4*)Wp;
        w1 = *(const float4*)(Wp + 4);
        const float* Xp = Xp0 + (size_t)(k0 + bk) * hw;
        x0 = *(const float4*)Xp;
        x1 = *(const float4*)(Xp + 4);
    };
    auto storeS = [&]() {
        As[akq + 0][am] = f2tf(w0.x);
        As[akq + 1][am] = f2tf(w0.y);
        As[akq + 2][am] = f2tf(w0.z);
        As[akq + 3][am] = f2tf(w0.w);
        As[akq + 4][am] = f2tf(w1.x);
        As[akq + 5][am] = f2tf(w1.y);
        As[akq + 6][am] = f2tf(w1.z);
        As[akq + 7][am] = f2tf(w1.w);
        *(uint4*)&Bs[bk][bn]     = make_uint4(f2tf(x0.x), f2tf(x0.y), f2tf(x0.z), f2tf(x0.w));
        *(uint4*)&Bs[bk][bn + 4] = make_uint4(f2tf(x1.x), f2tf(x1.y), f2tf(x1.z), f2tf(x1.w));
    };

    loadG(0);
    for (int kt = 0; kt < nK; kt++) {
        __syncthreads();
        storeS();
        __syncthreads();
        if (kt + 1 < nK) loadG((kt + 1) << 4);
        tile_mma(As, Bs, acc, lane, mbase, nbase);
    }

    const bool dobn = (bng != nullptr);
#pragma unroll
    for (int mt = 0; mt < 4; mt++) {
#pragma unroll
        for (int half = 0; half < 2; half++) {
            int o = to + mbase + mt * 16 + (lane >> 2) + half * 8;
            float bia = bias ? bias[o] : 0.0f;
            float sc = 1.0f, mn = 0.0f, bt = 0.0f;
            if (dobn) {
                sc = bng[o] * rsqrtf(bnv[o] + 1e-5f);
                mn = bnm[o];
                bt = bnb[o];
            }
            size_t rowb = ((size_t)b * O + o) * hw + tp;
#pragma unroll
            for (int nt = 0; nt < 4; nt++) {
                int n = nbase + nt * 8 + 2 * (lane & 3);
                float v0 = acc[mt][nt][half * 2 + 0] + bia;
                float v1 = acc[mt][nt][half * 2 + 1] + bia;
                if (addin) {
                    float2 ad = *(const float2*)(addin + rowb + n);
                    v0 += ad.x; v1 += ad.y;
                }
                if (dobn) {
                    v0 = fmaxf((v0 - mn) * sc + bt, 0.0f);
                    v1 = fmaxf((v1 - mn) * sc + bt, 0.0f);
                }
                *(float2*)(Y + rowb + n) = make_float2(v0, v1);
            }
        }
    }
}

// ---------------- generic 16-output projection ----------------
__global__ __launch_bounds__(256) void proj16g(
    const float* __restrict__ Wm, int ldw,
    const float* __restrict__ bias,
    const float* __restrict__ X, int K, int hw,
    float* __restrict__ Y, int accum)
{
    __shared__ float Ws[16 * 256];
    const int b = blockIdx.y;
    const int p = blockIdx.x * 256 + threadIdx.x;
    for (int i = threadIdx.x; i < 16 * K; i += 256)
        Ws[i] = Wm[(i / K) * ldw + (i % K)];
    __syncthreads();
    float* Yp = Y + (size_t)b * 16 * hw + p;
    float acc[16];
#pragma unroll
    for (int o = 0; o < 16; o++)
        acc[o] = accum ? Yp[(size_t)o * hw] : (bias ? bias[o] : 0.0f);
    const float* Xp = X + (size_t)b * K * hw + p;
#pragma unroll 4
    for (int i = 0; i < K; i++) {
        float xv = Xp[(size_t)i * hw];
#pragma unroll
        for (int o = 0; o < 16; o++) acc[o] += Ws[o * K + i] * xv;
    }
#pragma unroll
    for (int o = 0; o < 16; o++) Yp[(size_t)o * hw] = acc[o];
}

// ---------------- 4-way split-K projection (K=256 @ HWSZ, accumulates) ------------
__global__ __launch_bounds__(256) void proj16_splitk(
    const float* __restrict__ Wm, int ldw,
    const float* __restrict__ X,
    float* __restrict__ Y)
{
    __shared__ float Wsh[16 * 256];
    __shared__ float part[3][64][17];
    const int b  = blockIdx.y;
    const int px0 = blockIdx.x * 64;
    const int tid = threadIdx.x;
    const int pi = tid & 63;
    const int kg = tid >> 6;

    for (int i = tid; i < 4096; i += 256)
        Wsh[i] = Wm[(i >> 8) * ldw + (i & 255)];
    __syncthreads();

    float acc[16] = {};
    const float* Xp = X + ((size_t)b * 256 + kg * 64) * HWSZ + px0 + pi;
    const float* Wk = Wsh + kg * 64;
#pragma unroll 4
    for (int i = 0; i < 64; i++) {
        float xv = Xp[(size_t)i * HWSZ];
#pragma unroll
        for (int o = 0; o < 16; o++) acc[o] += Wk[o * 256 + i] * xv;
    }

    if (kg > 0) {
#pragma unroll
        for (int o = 0; o < 16; o++) part[kg - 1][pi][o] = acc[o];
    }
    __syncthreads();
    if (kg == 0) {
        float* Yp = Y + (size_t)b * 16 * HWSZ + px0 + pi;
#pragma unroll
        for (int o = 0; o < 16; o++)
            Yp[(size_t)o * HWSZ] += acc[o] + part[0][pi][o] + part[1][pi][o] + part[2][pi][o];
    }
}

// ---------------- 2-way split-K projection (K=128 @ HWSZ, bias, overwrite) ----------
__global__ __launch_bounds__(256) void proj16_splitk2(
    const float* __restrict__ Wm, int ldw,
    const float* __restrict__ bias,
    const float* __restrict__ X,
    float* __restrict__ Y)
{
    __shared__ float Wsh[16 * 128];
    __shared__ float part[128][17];
    const int b  = blockIdx.y;
    const int px0 = blockIdx.x * 128;
    const int tid = threadIdx.x;
    const int pi = tid & 127;
    const int kg = tid >> 7;           // 0..1, 64 channels each

    for (int i = tid; i < 2048; i += 256)
        Wsh[i] = Wm[(i >> 7) * ldw + (i & 127)];
    __syncthreads();

    float acc[16] = {};
    const float* Xp = X + ((size_t)b * 128 + kg * 64) * HWSZ + px0 + pi;
    const float* Wk = Wsh + kg * 64;
#pragma unroll 4
    for (int i = 0; i < 64; i++) {
        float xv = Xp[(size_t)i * HWSZ];
#pragma unroll
        for (int o = 0; o < 16; o++) acc[o] += Wk[o * 128 + i] * xv;
    }

    if (kg == 1) {
#pragma unroll
        for (int o = 0; o < 16; o++) part[pi][o] = acc[o];
    }
    __syncthreads();
    if (kg == 0) {
        float* Yp = Y + (size_t)b * 16 * HWSZ + px0 + pi;
#pragma unroll
        for (int o = 0; o < 16; o++)
            Yp[(size_t)o * HWSZ] = bias[o] + acc[o] + part[pi][o];
    }
}

// ---------------- criss-cross logits (raw) ----------------
__global__ __launch_bounds__(256) void eH_kernel(const float* __restrict__ pq,
                                                 const float* __restrict__ pk,
                                                 float* __restrict__ att)
{
    __shared__ float PQ[16][128];
    __shared__ float PK[16][128];
    const int w = blockIdx.x, b = blockIdx.y;
    for (int i = threadIdx.x; i < 2048; i += 256) {
        int c = i >> 7, h = i & 127;
        size_t idx = (((size_t)b * 16 + c) * 128 + h) * 128 + w;
        PQ[c][h] = pq[idx];
        PK[c][h] = pk[idx];
    }
    __syncthreads();
    const int x  = threadIdx.x & 127;
    const int h0 = threadIdx.x >> 7;
    for (int h = h0; h < 128; h += 2) {
        float s = 0.0f;
#pragma unroll
        for (int c = 0; c < 16; c++) s += PQ[c][h] * PK[c][x];
        if (h == x) s += NEGINF;
        att[(((size_t)b * 128 + h) * 128 + w) * 256 + x] = s;
    }
}

__global__ __launch_bounds__(256) void eW_kernel(const float* __restrict__ pq,
                                                 const float* __restrict__ pk,
                                                 float* __restrict__ att)
{
    __shared__ float PQ[16][128];
    __shared__ float PK[16][128];
    const int h = blockIdx.x, b = blockIdx.y;
    for (int i = threadIdx.x; i < 2048; i += 256) {
        int c = i >> 7, w = i & 127;
        size_t idx = (((size_t)b * 16 + c) * 128 + h) * 128 + w;
        PQ[c][w] = pq[idx];
        PK[c][w] = pk[idx];
    }
    __syncthreads();
    const int x  = threadIdx.x & 127;
    const int w0 = threadIdx.x >> 7;
    for (int w = w0; w < 128; w += 2) {
        float s = 0.0f;
#pragma unroll
        for (int c = 0; c < 16; c++) s += PQ[c][w] * PK[c][x];
        att[(((size_t)b * 128 + h) * 128 + w) * 256 + 128 + x] = s;
    }
}

// ---------------- aggH: U[c,h] = sum_x pv*exp(attH); also emits sumH[b,h,w] ----------
__global__ __launch_bounds__(256) void aggH_mma(const float* __restrict__ pv,
                                                const float* __restrict__ att,
                                                float* __restrict__ tmp,
                                                float* __restrict__ sumH)
{
    __shared__ unsigned As[16][136];
    __shared__ unsigned Bs[16][136];
    __shared__ float sums[128][2];
    const int w = blockIdx.x, b = blockIdx.y;
    const int tid  = threadIdx.x;
    const int warp = tid >> 5;
    const int lane = tid & 31;
    const int mbase = (warp >> 2) * 64;
    const int nbase = (warp & 3) * 32;

    const int cm = tid >> 1;
    const int xq = (tid & 1) * 8;

    float acc[4][4][4] = {};
    float esum = 0.0f;
    const float* pvp = pv + ((size_t)b * 128 + cm) * HWSZ + w;
    const float* atp = att + (((size_t)b * 128 + cm) * 128 + w) * 256;

    float av[8];
    float4 b0, b1;
    auto loadG = [&](int k0) {
#pragma unroll
        for (int j = 0; j < 8; j++) av[j] = pvp[(size_t)(k0 + xq + j) * 128];
        b0 = *(const float4*)(atp + k0 + xq);
        b1 = *(const float4*)(atp + k0 + xq + 4);
    };
    auto storeS = [&]() {
#pragma unroll
        for (int j = 0; j < 8; j++) As[xq + j][cm] = f2tf(av[j]);
        float e0 = __expf(b0.x), e1 = __expf(b0.y), e2 = __expf(b0.z), e3 = __expf(b0.w);
        float e4 = __expf(b1.x), e5 = __expf(b1.y), e6 = __expf(b1.z), e7 = __expf(b1.w);
        Bs[xq + 0][cm] = f2tf(e0);
        Bs[xq + 1][cm] = f2tf(e1);
        Bs[xq + 2][cm] = f2tf(e2);
        Bs[xq + 3][cm] = f2tf(e3);
        Bs[xq + 4][cm] = f2tf(e4);
        Bs[xq + 5][cm] = f2tf(e5);
        Bs[xq + 6][cm] = f2tf(e6);
        Bs[xq + 7][cm] = f2tf(e7);
        esum += ((e0 + e1) + (e2 + e3)) + ((e4 + e5) + (e6 + e7));
    };

    loadG(0);
    for (int kt = 0; kt < 8; kt++) {
        __syncthreads();
        storeS();
        __syncthreads();
        if (kt < 7) loadG((kt + 1) << 4);
        tile_mma(As, Bs, acc, lane, mbase, nbase);
    }

    sums[cm][tid & 1] = esum;
    __syncthreads();
    if (tid < 128)
        sumH[((size_t)b * 128 + tid) * 128 + w] = sums[tid][0] + sums[tid][1];

#pragma unroll
    for (int mt = 0; mt < 4; mt++)
#pragma unroll
        for (int half = 0; half < 2; half++) {
            int c = mbase + mt * 16 + (lane >> 2) + half * 8;
            size_t cb = ((size_t)b * 128 + c) * HWSZ + w;
#pragma unroll
            for (int nt = 0; nt < 4; nt++) {
                int h = nbase + nt * 8 + 2 * (lane & 3);
                tmp[cb + (size_t)h * 128]       = acc[mt][nt][half * 2 + 0];
                tmp[cb + (size_t)(h + 1) * 128] = acc[mt][nt][half * 2 + 1];
            }
        }
}

// ---------------- aggW: value += gamma*(U + V) / (sumH + sumW) ----------------
__global__ __launch_bounds__(256) void aggW_mma(const float* __restrict__ pv,
                                                const float* __restrict__ att,
                                                const float* __restrict__ sumH,
                                                const float* __restrict__ tmp,
                                                float* __restrict__ value,
                                                const float* __restrict__ gamma_p)
{
    __shared__ unsigned As[16][136];
    __shared__ unsigned Bs[16][136];
    __shared__ float sums[128][2];
    __shared__ float invs[128];
    const int h = blockIdx.x, b = blockIdx.y;
    const int tid  = threadIdx.x;
    const int warp = tid >> 5;
    const int lane = tid & 31;
    const int mbase = (warp >> 2) * 64;
    const int nbase = (warp & 3) * 32;

    const int cm = tid >> 1;
    const int xq = (tid & 1) * 8;

    float acc[4][4][4] = {};
    float esum = 0.0f;
    const float* pvp = pv + (((size_t)b * 128 + cm) * 128 + h) * 128;
    const float* atp = att + (((size_t)b * 128 + h) * 128 + cm) * 256 + 128;

    float4 a0, a1, b0, b1;
    auto loadG = [&](int k0) {
        a0 = *(const float4*)(pvp + k0 + xq);
        a1 = *(const float4*)(pvp + k0 + xq + 4);
        b0 = *(const float4*)(atp + k0 + xq);
        b1 = *(const float4*)(atp + k0 + xq + 4);
    };
    auto storeS = [&]() {
        As[xq + 0][cm] = f2tf(a0.x);
        As[xq + 1][cm] = f2tf(a0.y);
        As[xq + 2][cm] = f2tf(a0.z);
        As[xq + 3][cm] = f2tf(a0.w);
        As[xq + 4][cm] = f2tf(a1.x);
        As[xq + 5][cm] = f2tf(a1.y);
        As[xq + 6][cm] = f2tf(a1.z);
        As[xq + 7][cm] = f2tf(a1.w);
        float e0 = __expf(b0.x), e1 = __expf(b0.y), e2 = __expf(b0.z), e3 = __expf(b0.w);
        float e4 = __expf(b1.x), e5 = __expf(b1.y), e6 = __expf(b1.z), e7 = __expf(b1.w);
        Bs[xq + 0][cm] = f2tf(e0);
        Bs[xq + 1][cm] = f2tf(e1);
        Bs[xq + 2][cm] = f2tf(e2);
        Bs[xq + 3][cm] = f2tf(e3);
        Bs[xq + 4][cm] = f2tf(e4);
        Bs[xq + 5][cm] = f2tf(e5);
        Bs[xq + 6][cm] = f2tf(e6);
        Bs[xq + 7][cm] = f2tf(e7);
        esum += ((e0 + e1) + (e2 + e3)) + ((e4 + e5) + (e6 + e7));
    };

    loadG(0);
    for (int kt = 0; kt < 8; kt++) {
        __syncthreads();
        storeS();
        __syncthreads();
        if (kt < 7) loadG((kt + 1) << 4);
        tile_mma(As, Bs, acc, lane, mbase, nbase);
    }

    sums[cm][tid & 1] = esum;
    __syncthreads();
    if (tid < 128)
        invs[tid] = 1.0f / (sumH[((size_t)b * 128 + h) * 128 + tid]
                            + sums[tid][0] + sums[tid][1]);
    __syncthreads();

    const float g = *gamma_p;
#pragma unroll
    for (int mt = 0; mt < 4; mt++)
#pragma unroll
        for (int half = 0; half < 2; half++) {
            int c = mbase + mt * 16 + (lane >> 2) + half * 8;
            size_t rowb = (((size_t)b * 128 + c) * 128 + h) * 128;
#pragma unroll
            for (int nt = 0; nt < 4; nt++) {
                int n = nbase + nt * 8 + 2 * (lane & 3);
                float2 t = *(const float2*)(tmp + rowb + n);
                float2 v = *(const float2*)(value + rowb + n);
                v.x += g * (t.x + acc[mt][nt][half * 2 + 0]) * invs[n];
                v.y += g * (t.y + acc[mt][nt][half * 2 + 1]) * invs[n + 1];
                *(float2*)(value + rowb + n) = v;
            }
        }
}

// ---------------- launch ----------------
extern "C" void kernel_launch(void* const* d_in, const int* in_sizes, int n_in,
                              void* d_out, int out_size)
{
    const float* low   = (const float*)d_in[0];
    const float* high  = (const float*)d_in[1];
    const float* Wc1   = (const float*)d_in[2];
    const float* bc1   = (const float*)d_in[3];
    const float* Wc2   = (const float*)d_in[4];
    const float* bc2   = (const float*)d_in[5];
    const float* Wq    = (const float*)d_in[6];
    const float* bq    = (const float*)d_in[7];
    const float* Wk    = (const float*)d_in[8];
    const float* bk    = (const float*)d_in[9];
    const float* Wv    = (const float*)d_in[10];
    const float* bv    = (const float*)d_in[11];
    const float* gamma = (const float*)d_in[12];
    const float* Wb    = (const float*)d_in[13];
    const float* bng   = (const float*)d_in[14];
    const float* bnb   = (const float*)d_in[15];
    const float* bnm   = (const float*)d_in[16];
    const float* bnv   = (const float*)d_in[17];
    float* out = (float*)d_out;

    float *fbu, *value, *pv, *tmp, *pq, *pk, *att, *pqs, *vs, *fbs, *weff, *beff, *sumH;
    cudaGetSymbolAddress((void**)&fbu,   g_fbu);
    cudaGetSymbolAddress((void**)&value, g_value);
    cudaGetSymbolAddress((void**)&pv,    g_pv);
    cudaGetSymbolAddress((void**)&tmp,   g_tmp);
    cudaGetSymbolAddress((void**)&pq,    g_pq);
    cudaGetSymbolAddress((void**)&pk,    g_pk);
    cudaGetSymbolAddress((void**)&att,   g_att);
    cudaGetSymbolAddress((void**)&pqs,   g_pqs);
    cudaGetSymbolAddress((void**)&vs,    g_vs);
    cudaGetSymbolAddress((void**)&fbs,   g_fbs);
    cudaGetSymbolAddress((void**)&weff,  g_weff);
    cudaGetSymbolAddress((void**)&beff,  g_beff);
    cudaGetSymbolAddress((void**)&sumH,  g_sumH);

    // 0. fold Wq through Wc1 (query tensor never materialized)
    prep_weff<<<33, 256>>>(Wq, Wc1, bq, bc1, weff, beff);

    // 1. pq = upsample(Wq_eff_hi @ high) + Wq_eff_lo @ low
    proj16g<<<dim3(16, BB), 256>>>(weff, 512, beff, high, 256, 4096, pqs, 0);
    upsample_kernel<<<4096, 256>>>(pqs, pq);
    proj16_splitk<<<dim3(256, BB), 256>>>(weff + 256, 512, low, pq);

    // 2. value = upsample(Wc2 @ high + bc2)
    gemm_dual<<<dim3(32, 1, BB), 256>>>(Wc2, 256, bc2, high, 256, vs, 128, 4096,
                                        nullptr, nullptr, nullptr, nullptr, nullptr);
    upsample_kernel<<<32768, 256>>>(vs, value);

    // 3. fbu = upsample(Wb[:,128:] @ high)
    gemm_dual<<<dim3(32, 2, BB), 256>>>(Wb + 128, 384, nullptr, high, 256, fbs, 256, 4096,
                                        nullptr, nullptr, nullptr, nullptr, nullptr);
    upsample_kernel<<<65536, 256>>>(fbs, fbu);

    // 4. two criss-cross attention iterations (row-sums ride the agg staging)
    for (int it = 0; it < 2; it++) {
        proj16_splitk2<<<dim3(128, BB), 256>>>(Wk, 128, bk, value, pk);
        gemm_dual<<<dim3(128, 1, BB), 256>>>(Wv, 128, bv, value, 128, pv, 128, HWSZ,
                                             nullptr, nullptr, nullptr, nullptr, nullptr);
        eH_kernel<<<dim3(128, BB), 256>>>(pq, pk, att);
        eW_kernel<<<dim3(128, BB), 256>>>(pq, pk, att);
        aggH_mma<<<dim3(128, BB), 256>>>(pv, att, tmp, sumH);
        aggW_mma<<<dim3(128, BB), 256>>>(pv, att, sumH, tmp, value, gamma);
    }

    // 5. out = ReLU(BN(Wb[:,:128] @ value + fbu))
    gemm_dual<<<dim3(128, 2, BB), 256>>>(Wb, 384, nullptr, value, 128, out, 256, HWSZ,
                                         fbu, bng, bnb, bnm, bnv);
}

// round 14
// speedup vs baseline: 1.1380x; 1.0060x over previous
#include <cuda_runtime.h>
#include <math.h>

#define BB   4
#define HWSZ 16384        // 128*128

// ---------------- scratch (device globals: no allocation allowed) ----------------
__device__ float g_fbu  [16777216];  // upsampled Wb_hi@high (4,256,128,128)
__device__ float g_value[ 8388608];  // (4,128,128,128)
__device__ float g_pv   [ 8388608];
__device__ float g_tmp  [ 8388608];  // unnormalized U
__device__ float g_pq   [ 1048576];  // (4,16,128,128)
__device__ float g_pk   [ 1048576];
__device__ float g_pqs  [  262144];  // (4,16,64,64)
__device__ float g_vs   [ 2097152];  // (4,128,64,64)
__device__ float g_fbs  [ 4194304];  // (4,256,64,64)
__device__ float g_weff [    8192];  // Wq@Wc1 (16,512)
__device__ float g_beff [      16];
__device__ float g_sumH [   65536];  // (4,128,128) sum of exp over H-branch

// ---------------- tf32 helpers ----------------
__device__ __forceinline__ unsigned f2tf(float f) {
    unsigned r;
    asm("cvt.rna.tf32.f32 %0, %1;" : "=r"(r) : "f"(f));
    return r;
}

__device__ __forceinline__ void mma8(float* d, const unsigned* a, const unsigned* b) {
    asm("mma.sync.aligned.m16n8k8.row.col.f32.tf32.tf32.f32 "
        "{%0,%1,%2,%3},{%4,%5,%6,%7},{%8,%9},{%0,%1,%2,%3};"
        : "+f"(d[0]), "+f"(d[1]), "+f"(d[2]), "+f"(d[3])
        : "r"(a[0]), "r"(a[1]), "r"(a[2]), "r"(a[3]), "r"(b[0]), "r"(b[1]));
}

__device__ __forceinline__ void tile_mma(const unsigned (*As)[136],
                                         const unsigned (*Bs)[136],
                                         float acc[4][4][4],
                                         int lane, int mbase, int nbase)
{
#pragma unroll
    for (int kt = 0; kt < 2; kt++) {
        unsigned a[4][4], b[4][2];
        const int kb = kt * 8 + (lane & 3);
        const int rq = lane >> 2;
#pragma unroll
        for (int mt = 0; mt < 4; mt++) {
            int m = mbase + mt * 16 + rq;
            a[mt][0] = As[kb][m];
            a[mt][1] = As[kb][m + 8];
            a[mt][2] = As[kb + 4][m];
            a[mt][3] = As[kb + 4][m + 8];
        }
#pragma unroll
        for (int nt = 0; nt < 4; nt++) {
            int n = nbase + nt * 8 + rq;
            b[nt][0] = Bs[kb][n];
            b[nt][1] = Bs[kb + 4][n];
        }
#pragma unroll
        for (int mt = 0; mt < 4; mt++)
#pragma unroll
            for (int nt = 0; nt < 4; nt++)
                mma8(acc[mt][nt], a[mt], b[nt]);
    }
}

// ---------------- Wq_eff = Wq @ Wc1 ; b_eff = bq + Wq @ bc1 ----------------
__global__ __launch_bounds__(256) void prep_weff(
    const float* __restrict__ Wq, const float* __restrict__ Wc1,
    const float* __restrict__ bq, const float* __restrict__ bc1,
    float* __restrict__ weff, float* __restrict__ beff)
{
    int t = blockIdx.x * 256 + threadIdx.x;
    if (blockIdx.x < 32) {
        int o = t >> 9, j = t & 511;
        float s = 0.0f;
#pragma unroll 4
        for (int i = 0; i < 128; i++) s += Wq[o * 128 + i] * Wc1[i * 512 + j];
        weff[o * 512 + j] = s;
    } else if (threadIdx.x < 16) {
        int o = threadIdx.x;
        float s = bq[o];
        for (int i = 0; i < 128; i++) s += Wq[o * 128 + i] * bc1[i];
        beff[o] = s;
    }
}

// ---------------- bilinear 2x upsample ----------------
__global__ __launch_bounds__(256) void upsample_kernel(const float* __restrict__ in,
                                                       float* __restrict__ out) {
    int idx = blockIdx.x * 256 + threadIdx.x;
    int ox = idx & 127;
    int oy = (idx >> 7) & 127;
    int bc = idx >> 14;
    float fy = 0.5f * oy - 0.25f;
    float fx = 0.5f * ox - 0.25f;
    int y0 = (int)floorf(fy); float wy = fy - (float)y0;
    int x0 = (int)floorf(fx); float wx = fx - (float)x0;
    int y1 = min(y0 + 1, 63); y0 = max(y0, 0);
    int x1 = min(x0 + 1, 63); x0 = max(x0, 0);
    const float* p = in + (size_t)bc * 4096;
    float v00 = p[y0 * 64 + x0], v01 = p[y0 * 64 + x1];
    float v10 = p[y1 * 64 + x0], v11 = p[y1 * 64 + x1];
    float top = v00 + wx * (v01 - v00);
    float bot = v10 + wx * (v11 - v10);
    out[idx] = top + wy * (bot - top);
}

// ---------------- tf32 GEMM with register-prefetch pipelining ----------------
__global__ __launch_bounds__(256) void gemm_dual(
    const float* __restrict__ Wm, int ldw,
    const float* __restrict__ bias,
    const float* __restrict__ X, int I,
    float* __restrict__ Y, int O, int hw,
    const float* __restrict__ addin,
    const float* __restrict__ bng, const float* __restrict__ bnb,
    const float* __restrict__ bnm, const float* __restrict__ bnv)
{
    __shared__ unsigned As[16][136];
    __shared__ unsigned Bs[16][136];
    const int b  = blockIdx.z;
    const int to = blockIdx.y * 128;
    const int tp = blockIdx.x * 128;
    const int tid  = threadIdx.x;
    const int warp = tid >> 5;
    const int lane = tid & 31;
    const int mbase = (warp >> 2) * 64;
    const int nbase = (warp & 3) * 32;

    const int am  = tid >> 1;
    const int akq = (tid & 1) * 8;
    const int bk  = tid >> 4;
    const int bn  = (tid & 15) * 8;

    const float* Xp0 = X + (size_t)b * I * hw + tp + bn;
    const int nK = I >> 4;

    float acc[4][4][4] = {};
    float4 w0, w1, x0, x1;

    auto loadG = [&](int k0) {
        const float* Wp = Wm + (size_t)(to + am) * ldw + k0 + akq;
        w0 = *(const float4*)Wp;
        w1 = *(const float4*)(Wp + 4);
        const float* Xp = Xp0 + (size_t)(k0 + bk) * hw;
        x0 = *(const float4*)Xp;
        x1 = *(const float4*)(Xp + 4);
    };
    auto storeS = [&]() {
        As[akq + 0][am] = f2tf(w0.x);
        As[akq + 1][am] = f2tf(w0.y);
        As[akq + 2][am] = f2tf(w0.z);
        As[akq + 3][am] = f2tf(w0.w);
        As[akq + 4][am] = f2tf(w1.x);
        As[akq + 5][am] = f2tf(w1.y);
        As[akq + 6][am] = f2tf(w1.z);
        As[akq + 7][am] = f2tf(w1.w);
        *(uint4*)&Bs[bk][bn]     = make_uint4(f2tf(x0.x), f2tf(x0.y), f2tf(x0.z), f2tf(x0.w));
        *(uint4*)&Bs[bk][bn + 4] = make_uint4(f2tf(x1.x), f2tf(x1.y), f2tf(x1.z), f2tf(x1.w));
    };

    loadG(0);
    for (int kt = 0; kt < nK; kt++) {
        __syncthreads();
        storeS();
        __syncthreads();
        if (kt + 1 < nK) loadG((kt + 1) << 4);
        tile_mma(As, Bs, acc, lane, mbase, nbase);
    }

    const bool dobn = (bng != nullptr);
#pragma unroll
    for (int mt = 0; mt < 4; mt++) {
#pragma unroll
        for (int half = 0; half < 2; half++) {
            int o = to + mbase + mt * 16 + (lane >> 2) + half * 8;
            float bia = bias ? bias[o] : 0.0f;
            float sc = 1.0f, mn = 0.0f, bt = 0.0f;
            if (dobn) {
                sc = bng[o] * rsqrtf(bnv[o] + 1e-5f);
                mn = bnm[o];
                bt = bnb[o];
            }
            size_t rowb = ((size_t)b * O + o) * hw + tp;
#pragma unroll
            for (int nt = 0; nt < 4; nt++) {
                int n = nbase + nt * 8 + 2 * (lane & 3);
                float v0 = acc[mt][nt][half * 2 + 0] + bia;
                float v1 = acc[mt][nt][half * 2 + 1] + bia;
                if (addin) {
                    float2 ad = *(const float2*)(addin + rowb + n);
                    v0 += ad.x; v1 += ad.y;
                }
                if (dobn) {
                    v0 = fmaxf((v0 - mn) * sc + bt, 0.0f);
                    v1 = fmaxf((v1 - mn) * sc + bt, 0.0f);
                }
                *(float2*)(Y + rowb + n) = make_float2(v0, v1);
            }
        }
    }
}

// ---------------- generic 16-output projection ----------------
__global__ __launch_bounds__(256) void proj16g(
    const float* __restrict__ Wm, int ldw,
    const float* __restrict__ bias,
    const float* __restrict__ X, int K, int hw,
    float* __restrict__ Y, int accum)
{
    __shared__ float Ws[16 * 256];
    const int b = blockIdx.y;
    const int p = blockIdx.x * 256 + threadIdx.x;
    for (int i = threadIdx.x; i < 16 * K; i += 256)
        Ws[i] = Wm[(i / K) * ldw + (i % K)];
    __syncthreads();
    float* Yp = Y + (size_t)b * 16 * hw + p;
    float acc[16];
#pragma unroll
    for (int o = 0; o < 16; o++)
        acc[o] = accum ? Yp[(size_t)o * hw] : (bias ? bias[o] : 0.0f);
    const float* Xp = X + (size_t)b * K * hw + p;
#pragma unroll 4
    for (int i = 0; i < K; i++) {
        float xv = Xp[(size_t)i * hw];
#pragma unroll
        for (int o = 0; o < 16; o++) acc[o] += Ws[o * K + i] * xv;
    }
#pragma unroll
    for (int o = 0; o < 16; o++) Yp[(size_t)o * hw] = acc[o];
}

// ---------------- 4-way split-K projection (K=256 @ HWSZ, accumulates) ------------
__global__ __launch_bounds__(256) void proj16_splitk(
    const float* __restrict__ Wm, int ldw,
    const float* __restrict__ X,
    float* __restrict__ Y)
{
    __shared__ float Wsh[16 * 256];
    __shared__ float part[3][64][17];
    const int b  = blockIdx.y;
    const int px0 = blockIdx.x * 64;
    const int tid = threadIdx.x;
    const int pi = tid & 63;
    const int kg = tid >> 6;

    for (int i = tid; i < 4096; i += 256)
        Wsh[i] = Wm[(i >> 8) * ldw + (i & 255)];
    __syncthreads();

    float acc[16] = {};
    const float* Xp = X + ((size_t)b * 256 + kg * 64) * HWSZ + px0 + pi;
    const float* Wk = Wsh + kg * 64;
#pragma unroll 4
    for (int i = 0; i < 64; i++) {
        float xv = Xp[(size_t)i * HWSZ];
#pragma unroll
        for (int o = 0; o < 16; o++) acc[o] += Wk[o * 256 + i] * xv;
    }

    if (kg > 0) {
#pragma unroll
        for (int o = 0; o < 16; o++) part[kg - 1][pi][o] = acc[o];
    }
    __syncthreads();
    if (kg == 0) {
        float* Yp = Y + (size_t)b * 16 * HWSZ + px0 + pi;
#pragma unroll
        for (int o = 0; o < 16; o++)
            Yp[(size_t)o * HWSZ] += acc[o] + part[0][pi][o] + part[1][pi][o] + part[2][pi][o];
    }
}

// ---------------- 2-way split-K projection (K=128 @ HWSZ, bias, overwrite) ----------
__global__ __launch_bounds__(256) void proj16_splitk2(
    const float* __restrict__ Wm, int ldw,
    const float* __restrict__ bias,
    const float* __restrict__ X,
    float* __restrict__ Y)
{
    __shared__ float Wsh[16 * 128];
    __shared__ float part[128][17];
    const int b  = blockIdx.y;
    const int px0 = blockIdx.x * 128;
    const int tid = threadIdx.x;
    const int pi = tid & 127;
    const int kg = tid >> 7;

    for (int i = tid; i < 2048; i += 256)
        Wsh[i] = Wm[(i >> 7) * ldw + (i & 127)];
    __syncthreads();

    float acc[16] = {};
    const float* Xp = X + ((size_t)b * 128 + kg * 64) * HWSZ + px0 + pi;
    const float* Wk = Wsh + kg * 64;
#pragma unroll 4
    for (int i = 0; i < 64; i++) {
        float xv = Xp[(size_t)i * HWSZ];
#pragma unroll
        for (int o = 0; o < 16; o++) acc[o] += Wk[o * 128 + i] * xv;
    }

    if (kg == 1) {
#pragma unroll
        for (int o = 0; o < 16; o++) part[pi][o] = acc[o];
    }
    __syncthreads();
    if (kg == 0) {
        float* Yp = Y + (size_t)b * 16 * HWSZ + px0 + pi;
#pragma unroll
        for (int o = 0; o < 16; o++)
            Yp[(size_t)o * HWSZ] = bias[o] + acc[o] + part[pi][o];
    }
}

// ---------------- fused aggH: logits+exp computed in staging; U -> tmp; sumH out ------
// block (b,w): E[h,x] = exp(sum_c pq[c,h,w]*pk[c,x,w]), 0 on diag.
__global__ __launch_bounds__(256) void aggH_mma(const float* __restrict__ pq,
                                                const float* __restrict__ pk,
                                                const float* __restrict__ pv,
                                                float* __restrict__ tmp,
                                                float* __restrict__ sumH)
{
    __shared__ unsigned As[16][136];
    __shared__ unsigned Bs[16][136];
    __shared__ float PQ[16][128];
    __shared__ float PK[16][128];
    __shared__ float sums[128][2];
    const int w = blockIdx.x, b = blockIdx.y;
    const int tid  = threadIdx.x;
    const int warp = tid >> 5;
    const int lane = tid & 31;
    const int mbase = (warp >> 2) * 64;
    const int nbase = (warp & 3) * 32;

    const int cm = tid >> 1;          // h-row this thread stages (and pv channel)
    const int xq = (tid & 1) * 8;

    // load pq/pk columns at width w
    for (int i = tid; i < 2048; i += 256) {
        int c = i >> 7, h = i & 127;
        size_t idx = (((size_t)b * 16 + c) * 128 + h) * 128 + w;
        PQ[c][h] = pq[idx];
        PK[c][h] = pk[idx];
    }

    float acc[4][4][4] = {};
    float esum = 0.0f;
    const float* pvp = pv + ((size_t)b * 128 + cm) * HWSZ + w;

    float av[8];
    auto loadG = [&](int k0) {
#pragma unroll
        for (int j = 0; j < 8; j++) av[j] = pvp[(size_t)(k0 + xq + j) * 128];
    };
    auto storeS = [&](int k0) {
#pragma unroll
        for (int j = 0; j < 8; j++) As[xq + j][cm] = f2tf(av[j]);
#pragma unroll
        for (int j = 0; j < 8; j++) {
            int x = k0 + xq + j;
            float s = 0.0f;
#pragma unroll
            for (int c = 0; c < 16; c++) s += PQ[c][cm] * PK[c][x];
            float e = (x == cm) ? 0.0f : __expf(s);
            Bs[xq + j][cm] = f2tf(e);
            esum += e;
        }
    };

    loadG(0);
    for (int kt = 0; kt < 8; kt++) {
        __syncthreads();              // 1st iter: publishes PQ/PK; later: guards smem reuse
        storeS(kt << 4);
        __syncthreads();
        if (kt < 7) loadG((kt + 1) << 4);
        tile_mma(As, Bs, acc, lane, mbase, nbase);
    }

    sums[cm][tid & 1] = esum;
    __syncthreads();
    if (tid < 128)
        sumH[((size_t)b * 128 + tid) * 128 + w] = sums[tid][0] + sums[tid][1];

#pragma unroll
    for (int mt = 0; mt < 4; mt++)
#pragma unroll
        for (int half = 0; half < 2; half++) {
            int c = mbase + mt * 16 + (lane >> 2) + half * 8;
            size_t cb = ((size_t)b * 128 + c) * HWSZ + w;
#pragma unroll
            for (int nt = 0; nt < 4; nt++) {
                int h = nbase + nt * 8 + 2 * (lane & 3);
                tmp[cb + (size_t)h * 128]       = acc[mt][nt][half * 2 + 0];
                tmp[cb + (size_t)(h + 1) * 128] = acc[mt][nt][half * 2 + 1];
            }
        }
}

// ---------------- fused aggW: value += gamma*(U + V) / (sumH + sumW) ----------------
// block (b,h): E[w,x] = exp(sum_c pq[c,h,w]*pk[c,h,x]).
__global__ __launch_bounds__(256) void aggW_mma(const float* __restrict__ pq,
                                                const float* __restrict__ pk,
                                                const float* __restrict__ pv,
                                                const float* __restrict__ sumH,
                                                const float* __restrict__ tmp,
                                                float* __restrict__ value,
                                                const float* __restrict__ gamma_p)
{
    __shared__ unsigned As[16][136];
    __shared__ unsigned Bs[16][136];
    __shared__ float PQ[16][128];
    __shared__ float PK[16][128];
    __shared__ float sums[128][2];
    __shared__ float invs[128];
    const int h = blockIdx.x, b = blockIdx.y;
    const int tid  = threadIdx.x;
    const int warp = tid >> 5;
    const int lane = tid & 31;
    const int mbase = (warp >> 2) * 64;
    const int nbase = (warp & 3) * 32;

    const int cm = tid >> 1;          // w-row this thread stages (and pv channel)
    const int xq = (tid & 1) * 8;

    // load pq/pk rows at height h (contiguous)
    for (int i = tid; i < 2048; i += 256) {
        int c = i >> 7, x = i & 127;
        size_t idx = (((size_t)b * 16 + c) * 128 + h) * 128 + x;
        PQ[c][x] = pq[idx];
        PK[c][x] = pk[idx];
    }

    float acc[4][4][4] = {};
    float esum = 0.0f;
    const float* pvp = pv + (((size_t)b * 128 + cm) * 128 + h) * 128;

    float4 a0, a1;
    auto loadG = [&](int k0) {
        a0 = *(const float4*)(pvp + k0 + xq);
        a1 = *(const float4*)(pvp + k0 + xq + 4);
    };
    auto storeS = [&](int k0) {
        As[xq + 0][cm] = f2tf(a0.x);
        As[xq + 1][cm] = f2tf(a0.y);
        As[xq + 2][cm] = f2tf(a0.z);
        As[xq + 3][cm] = f2tf(a0.w);
        As[xq + 4][cm] = f2tf(a1.x);
        As[xq + 5][cm] = f2tf(a1.y);
        As[xq + 6][cm] = f2tf(a1.z);
        As[xq + 7][cm] = f2tf(a1.w);
#pragma unroll
        for (int j = 0; j < 8; j++) {
            int x = k0 + xq + j;
            float s = 0.0f;
#pragma unroll
            for (int c = 0; c < 16; c++) s += PQ[c][cm] * PK[c][x];
            float e = __expf(s);
            Bs[xq + j][cm] = f2tf(e);
            esum += e;
        }
    };

    loadG(0);
    for (int kt = 0; kt < 8; kt++) {
        __syncthreads();
        storeS(kt << 4);
        __syncthreads();
        if (kt < 7) loadG((kt + 1) << 4);
        tile_mma(As, Bs, acc, lane, mbase, nbase);
    }

    sums[cm][tid & 1] = esum;
    __syncthreads();
    if (tid < 128)
        invs[tid] = 1.0f / (sumH[((size_t)b * 128 + h) * 128 + tid]
                            + sums[tid][0] + sums[tid][1]);
    __syncthreads();

    const float g = *gamma_p;
#pragma unroll
    for (int mt = 0; mt < 4; mt++)
#pragma unroll
        for (int half = 0; half < 2; half++) {
            int c = mbase + mt * 16 + (lane >> 2) + half * 8;
            size_t rowb = (((size_t)b * 128 + c) * 128 + h) * 128;
#pragma unroll
            for (int nt = 0; nt < 4; nt++) {
                int n = nbase + nt * 8 + 2 * (lane & 3);
                float2 t = *(const float2*)(tmp + rowb + n);
                float2 v = *(const float2*)(value + rowb + n);
                v.x += g * (t.x + acc[mt][nt][half * 2 + 0]) * invs[n];
                v.y += g * (t.y + acc[mt][nt][half * 2 + 1]) * invs[n + 1];
                *(float2*)(value + rowb + n) = v;
            }
        }
}

// ---------------- launch ----------------
extern "C" void kernel_launch(void* const* d_in, const int* in_sizes, int n_in,
                              void* d_out, int out_size)
{
    const float* low   = (const float*)d_in[0];
    const float* high  = (const float*)d_in[1];
    const float* Wc1   = (const float*)d_in[2];
    const float* bc1   = (const float*)d_in[3];
    const float* Wc2   = (const float*)d_in[4];
    const float* bc2   = (const float*)d_in[5];
    const float* Wq    = (const float*)d_in[6];
    const float* bq    = (const float*)d_in[7];
    const float* Wk    = (const float*)d_in[8];
    const float* bk    = (const float*)d_in[9];
    const float* Wv    = (const float*)d_in[10];
    const float* bv    = (const float*)d_in[11];
    const float* gamma = (const float*)d_in[12];
    const float* Wb    = (const float*)d_in[13];
    const float* bng   = (const float*)d_in[14];
    const float* bnb   = (const float*)d_in[15];
    const float* bnm   = (const float*)d_in[16];
    const float* bnv   = (const float*)d_in[17];
    float* out = (float*)d_out;

    float *fbu, *value, *pv, *tmp, *pq, *pk, *pqs, *vs, *fbs, *weff, *beff, *sumH;
    cudaGetSymbolAddress((void**)&fbu,   g_fbu);
    cudaGetSymbolAddress((void**)&value, g_value);
    cudaGetSymbolAddress((void**)&pv,    g_pv);
    cudaGetSymbolAddress((void**)&tmp,   g_tmp);
    cudaGetSymbolAddress((void**)&pq,    g_pq);
    cudaGetSymbolAddress((void**)&pk,    g_pk);
    cudaGetSymbolAddress((void**)&pqs,   g_pqs);
    cudaGetSymbolAddress((void**)&vs,    g_vs);
    cudaGetSymbolAddress((void**)&fbs,   g_fbs);
    cudaGetSymbolAddress((void**)&weff,  g_weff);
    cudaGetSymbolAddress((void**)&beff,  g_beff);
    cudaGetSymbolAddress((void**)&sumH,  g_sumH);

    // 0. fold Wq through Wc1 (query tensor never materialized)
    prep_weff<<<33, 256>>>(Wq, Wc1, bq, bc1, weff, beff);

    // 1. pq = upsample(Wq_eff_hi @ high) + Wq_eff_lo @ low
    proj16g<<<dim3(16, BB), 256>>>(weff, 512, beff, high, 256, 4096, pqs, 0);
    upsample_kernel<<<4096, 256>>>(pqs, pq);
    proj16_splitk<<<dim3(256, BB), 256>>>(weff + 256, 512, low, pq);

    // 2. value = upsample(Wc2 @ high + bc2)
    gemm_dual<<<dim3(32, 1, BB), 256>>>(Wc2, 256, bc2, high, 256, vs, 128, 4096,
                                        nullptr, nullptr, nullptr, nullptr, nullptr);
    upsample_kernel<<<32768, 256>>>(vs, value);

    // 3. fbu = upsample(Wb[:,128:] @ high)
    gemm_dual<<<dim3(32, 2, BB), 256>>>(Wb + 128, 384, nullptr, high, 256, fbs, 256, 4096,
                                        nullptr, nullptr, nullptr, nullptr, nullptr);
    upsample_kernel<<<65536, 256>>>(fbs, fbu);

    // 4. two criss-cross attention iterations — logits computed inside agg staging
    for (int it = 0; it < 2; it++) {
        proj16_splitk2<<<dim3(128, BB), 256>>>(Wk, 128, bk, value, pk);
        gemm_dual<<<dim3(128, 1, BB), 256>>>(Wv, 128, bv, value, 128, pv, 128, HWSZ,
                                             nullptr, nullptr, nullptr, nullptr, nullptr);
        aggH_mma<<<dim3(128, BB), 256>>>(pq, pk, pv, tmp, sumH);
        aggW_mma<<<dim3(128, BB), 256>>>(pq, pk, pv, sumH, tmp, value, gamma);
    }

    // 5. out = ReLU(BN(Wb[:,:128] @ value + fbu))
    gemm_dual<<<dim3(128, 2, BB), 256>>>(Wb, 384, nullptr, value, 128, out, 256, HWSZ,
                                         fbu, bng, bnb, bnm, bnv);
}